// round 2
// baseline (speedup 1.0000x reference)
#include <cuda_runtime.h>
#include <math.h>

#define BATCH   2
#define S_LEN   2048
#define DEMB    1024
#define NHEADS  16
#define DHEAD   64

// Scratch (allocation-free rule: __device__ globals)
__device__ float g_qkv[BATCH * S_LEN * 3 * DEMB];   // [B, S, 3D]
__device__ float g_att[BATCH * S_LEN * DEMB];       // [B, S, D]

// ---------------------------------------------------------------------------
// SGEMM with fused bias:  C[M,N] = A[M,K] @ W[N,K]^T + bias[N]
// BM=128, BN=128, BK=16, 256 threads, 8x8 register tile per thread.
// M % 128 == 0, N % 128 == 0, K % 16 == 0 (true for all our shapes).
// ---------------------------------------------------------------------------
__global__ __launch_bounds__(256)
void sgemm_bias(const float* __restrict__ A, const float* __restrict__ W,
                const float* __restrict__ bias, float* __restrict__ C,
                int M, int N, int K)
{
    const int BM = 128, BN = 128, BK = 16;
    __shared__ float As[BK][BM];
    __shared__ float Bs[BK][BN];

    const int tid = threadIdx.x;
    const int m0 = blockIdx.y * BM;
    const int n0 = blockIdx.x * BN;
    const int tx = tid & 15;        // 0..15
    const int ty = tid >> 4;        // 0..15

    const int lr = tid >> 2;        // 0..63  (row within tile half)
    const int lk = (tid & 3) * 4;   // 0,4,8,12

    float acc[8][8];
    #pragma unroll
    for (int i = 0; i < 8; i++)
        #pragma unroll
        for (int j = 0; j < 8; j++) acc[i][j] = 0.0f;

    const float* Aptr0 = A + (size_t)(m0 + lr) * K + lk;
    const float* Aptr1 = A + (size_t)(m0 + lr + 64) * K + lk;
    const float* Wptr0 = W + (size_t)(n0 + lr) * K + lk;
    const float* Wptr1 = W + (size_t)(n0 + lr + 64) * K + lk;

    for (int k0 = 0; k0 < K; k0 += BK) {
        float4 a0 = *(const float4*)(Aptr0 + k0);
        float4 a1 = *(const float4*)(Aptr1 + k0);
        float4 b0 = *(const float4*)(Wptr0 + k0);
        float4 b1 = *(const float4*)(Wptr1 + k0);

        __syncthreads();   // previous iter's reads done before overwrite
        As[lk + 0][lr] = a0.x; As[lk + 1][lr] = a0.y;
        As[lk + 2][lr] = a0.z; As[lk + 3][lr] = a0.w;
        As[lk + 0][lr + 64] = a1.x; As[lk + 1][lr + 64] = a1.y;
        As[lk + 2][lr + 64] = a1.z; As[lk + 3][lr + 64] = a1.w;
        Bs[lk + 0][lr] = b0.x; Bs[lk + 1][lr] = b0.y;
        Bs[lk + 2][lr] = b0.z; Bs[lk + 3][lr] = b0.w;
        Bs[lk + 0][lr + 64] = b1.x; Bs[lk + 1][lr + 64] = b1.y;
        Bs[lk + 2][lr + 64] = b1.z; Bs[lk + 3][lr + 64] = b1.w;
        __syncthreads();

        #pragma unroll
        for (int kk = 0; kk < BK; kk++) {
            float a[8], b[8];
            *(float4*)&a[0] = *(const float4*)&As[kk][ty * 8];
            *(float4*)&a[4] = *(const float4*)&As[kk][ty * 8 + 4];
            *(float4*)&b[0] = *(const float4*)&Bs[kk][tx * 8];
            *(float4*)&b[4] = *(const float4*)&Bs[kk][tx * 8 + 4];
            #pragma unroll
            for (int i = 0; i < 8; i++)
                #pragma unroll
                for (int j = 0; j < 8; j++)
                    acc[i][j] = fmaf(a[i], b[j], acc[i][j]);
        }
    }

    // epilogue: bias + store
    float bv[8];
    #pragma unroll
    for (int j = 0; j < 8; j++) bv[j] = bias[n0 + tx * 8 + j];

    #pragma unroll
    for (int i = 0; i < 8; i++) {
        int m = m0 + ty * 8 + i;
        float* crow = C + (size_t)m * N + n0 + tx * 8;
        float4 o0, o1;
        o0.x = acc[i][0] + bv[0]; o0.y = acc[i][1] + bv[1];
        o0.z = acc[i][2] + bv[2]; o0.w = acc[i][3] + bv[3];
        o1.x = acc[i][4] + bv[4]; o1.y = acc[i][5] + bv[5];
        o1.z = acc[i][6] + bv[6]; o1.w = acc[i][7] + bv[7];
        *(float4*)(crow + 0) = o0;
        *(float4*)(crow + 4) = o1;
    }
}

// ---------------------------------------------------------------------------
// Flash attention, fp32, one thread per query row.
// qkv layout [B, S, 3D]: q at col h*64, k at 1024 + h*64, v at 2048 + h*64.
// Output att[b, s, h*64 + d]  (== score.transpose(0,2,1,3).reshape(B,S,D))
// ---------------------------------------------------------------------------
#define TQ 128
#define TK 64

__global__ __launch_bounds__(128)
void flash_attn(const float* __restrict__ qkv, const int* __restrict__ maskp,
                float* __restrict__ att)
{
    const int qi = threadIdx.x;              // 0..127
    const int q0 = blockIdx.x * TQ;
    const int h  = blockIdx.y;
    const int b  = blockIdx.z;
    const int gq = q0 + qi;
    const int D3 = 3 * DEMB;

    const float* base = qkv + (size_t)b * S_LEN * D3;
    const int mask = *maskp;

    // Q row into registers
    float q[DHEAD];
    {
        const float4* qp = (const float4*)(base + (size_t)gq * D3 + h * DHEAD);
        #pragma unroll
        for (int i = 0; i < 16; i++) {
            float4 v = qp[i];
            q[4 * i + 0] = v.x; q[4 * i + 1] = v.y;
            q[4 * i + 2] = v.z; q[4 * i + 3] = v.w;
        }
    }

    __shared__ float Ks[TK][DHEAD];
    __shared__ float Vs[TK][DHEAD];

    float acc[DHEAD];
    #pragma unroll
    for (int d = 0; d < DHEAD; d++) acc[d] = 0.0f;
    float m = -INFINITY, l = 0.0f;

    const int kend = mask ? (q0 + TQ) : S_LEN;   // exclusive bound for k0
    const float scale = 0.125f;                  // 1/sqrt(64)

    for (int k0 = 0; k0 < kend; k0 += TK) {
        __syncthreads();
        {
            int r = threadIdx.x >> 1;            // 0..63
            int c = (threadIdx.x & 1) * 32;      // 0 or 32
            const float4* kp = (const float4*)(base + (size_t)(k0 + r) * D3 + DEMB + h * DHEAD + c);
            const float4* vp = (const float4*)(base + (size_t)(k0 + r) * D3 + 2 * DEMB + h * DHEAD + c);
            float4* ks = (float4*)&Ks[r][c];
            float4* vs = (float4*)&Vs[r][c];
            #pragma unroll
            for (int i = 0; i < 8; i++) {
                ks[i] = kp[i];
                vs[i] = vp[i];
            }
        }
        __syncthreads();

        int jlim = TK;
        if (mask && (k0 + TK - 1 > q0)) {        // boundary tile for this block
            jlim = gq - k0 + 1;
            if (jlim > TK) jlim = TK;
            // jlim <= 0 -> loop skipped
        }

        for (int j = 0; j < jlim; j++) {
            float s = 0.0f;
            const float4* kr = (const float4*)Ks[j];
            #pragma unroll
            for (int i = 0; i < 16; i++) {
                float4 kv = kr[i];
                s = fmaf(q[4 * i + 0], kv.x, s);
                s = fmaf(q[4 * i + 1], kv.y, s);
                s = fmaf(q[4 * i + 2], kv.z, s);
                s = fmaf(q[4 * i + 3], kv.w, s);
            }
            s *= scale;

            float mnew = fmaxf(m, s);
            float p = __expf(s - mnew);
            if (mnew > m) {
                float alpha = __expf(m - mnew);
                l *= alpha;
                #pragma unroll
                for (int d = 0; d < DHEAD; d++) acc[d] *= alpha;
                m = mnew;
            }
            l += p;
            const float4* vr = (const float4*)Vs[j];
            #pragma unroll
            for (int i = 0; i < 16; i++) {
                float4 vv = vr[i];
                acc[4 * i + 0] = fmaf(p, vv.x, acc[4 * i + 0]);
                acc[4 * i + 1] = fmaf(p, vv.y, acc[4 * i + 1]);
                acc[4 * i + 2] = fmaf(p, vv.z, acc[4 * i + 2]);
                acc[4 * i + 3] = fmaf(p, vv.w, acc[4 * i + 3]);
            }
        }
    }

    const float inv = 1.0f / l;
    float4* op = (float4*)(att + ((size_t)b * S_LEN + gq) * DEMB + h * DHEAD);
    #pragma unroll
    for (int i = 0; i < 16; i++) {
        float4 o;
        o.x = acc[4 * i + 0] * inv; o.y = acc[4 * i + 1] * inv;
        o.z = acc[4 * i + 2] * inv; o.w = acc[4 * i + 3] * inv;
        op[i] = o;
    }
}

// ---------------------------------------------------------------------------
extern "C" void kernel_launch(void* const* d_in, const int* in_sizes, int n_in,
                              void* d_out, int out_size)
{
    const float* x     = (const float*)d_in[0];   // [2,2048,1024]
    const float* w_in  = (const float*)d_in[1];   // [3072,1024]
    const float* b_in  = (const float*)d_in[2];   // [3072]
    const float* w_out = (const float*)d_in[3];   // [1024,1024]
    const float* b_out = (const float*)d_in[4];   // [1024]
    const int*   maskp = (const int*)d_in[5];     // apply_mask
    float* out = (float*)d_out;                   // [2,2048,1024]

    void *qkv_p = nullptr, *att_p = nullptr;
    cudaGetSymbolAddress(&qkv_p, g_qkv);
    cudaGetSymbolAddress(&att_p, g_att);
    float* qkv = (float*)qkv_p;
    float* att = (float*)att_p;

    const int M = BATCH * S_LEN;   // 4096

    // 1) QKV projection: [4096,1024] @ [3072,1024]^T + b_in
    {
        dim3 grid(3 * DEMB / 128, M / 128);
        sgemm_bias<<<grid, 256>>>(x, w_in, b_in, qkv, M, 3 * DEMB, DEMB);
    }

    // 2) causal flash attention per (tile, head, batch)
    {
        dim3 grid(S_LEN / TQ, NHEADS, BATCH);
        flash_attn<<<grid, 128>>>(qkv, maskp, att);
    }

    // 3) output projection: [4096,1024] @ [1024,1024]^T + b_out
    {
        dim3 grid(DEMB / 128, M / 128);
        sgemm_bias<<<grid, 256>>>(att, w_out, b_out, out, M, DEMB, DEMB);
    }
}

// round 3
// speedup vs baseline: 3.6643x; 3.6643x over previous
#include <cuda_runtime.h>
#include <math.h>

#define BATCH   2
#define S_LEN   2048
#define DEMB    1024
#define NHEADS  16
#define DHEAD   64

// Scratch (allocation-free rule: __device__ globals)
__device__ float g_qkv[BATCH * S_LEN * 3 * DEMB];   // [B, S, 3D]
__device__ float g_att[BATCH * S_LEN * DEMB];       // [B, S, D]

// ---------------------------------------------------------------------------
// helpers: tf32 convert + m16n8k8 tf32 mma
// ---------------------------------------------------------------------------
__device__ __forceinline__ unsigned f2tf(float f) {
    unsigned u;
    asm("cvt.rna.tf32.f32 %0, %1;" : "=r"(u) : "f"(f));
    return u;
}

__device__ __forceinline__ void mma_tf32(float* c, const unsigned* a, const unsigned* b) {
    asm volatile(
        "mma.sync.aligned.m16n8k8.row.col.f32.tf32.tf32.f32 "
        "{%0,%1,%2,%3}, {%4,%5,%6,%7}, {%8,%9}, {%0,%1,%2,%3};"
        : "+f"(c[0]), "+f"(c[1]), "+f"(c[2]), "+f"(c[3])
        : "r"(a[0]), "r"(a[1]), "r"(a[2]), "r"(a[3]),
          "r"(b[0]), "r"(b[1]));
}

// ---------------------------------------------------------------------------
// tf32 GEMM with fused bias: C[M,N] = A[M,K] @ W[N,K]^T + bias[N]
// BM=BN=128, BK=32. 256 threads = 8 warps in 2(m) x 4(n); warp tile 64x32.
// ---------------------------------------------------------------------------
#define GBM 128
#define GBN 128
#define GBK 32
#define GLD (GBK + 4)   // padded row length (in 4B words)

__global__ __launch_bounds__(256)
void gemm_tf32(const float* __restrict__ A, const float* __restrict__ W,
               const float* __restrict__ bias, float* __restrict__ C,
               int M, int N, int K)
{
    __shared__ unsigned As[GBM][GLD];
    __shared__ unsigned Bs[GBN][GLD];

    const int tid  = threadIdx.x;
    const int wid  = tid >> 5;
    const int lane = tid & 31;
    const int wm   = wid >> 2;     // 0..1
    const int wn   = wid & 3;      // 0..3
    const int qr   = lane >> 2;    // 0..7
    const int qc   = lane & 3;     // 0..3
    const int m0 = blockIdx.y * GBM;
    const int n0 = blockIdx.x * GBN;

    float acc[4][4][4];
    #pragma unroll
    for (int mi = 0; mi < 4; mi++)
        #pragma unroll
        for (int ni = 0; ni < 4; ni++)
            #pragma unroll
            for (int c = 0; c < 4; c++) acc[mi][ni][c] = 0.0f;

    const float* Ab = A + (size_t)m0 * K;
    const float* Wb = W + (size_t)n0 * K;

    // prefetch first k-tile (128x32 floats = 1024 float4, 4 per thread)
    float4 ra[4], rb[4];
    #pragma unroll
    for (int i = 0; i < 4; i++) {
        int idx = i * 256 + tid;
        int r = idx >> 3, c = (idx & 7) * 4;
        ra[i] = *(const float4*)(Ab + (size_t)r * K + c);
        rb[i] = *(const float4*)(Wb + (size_t)r * K + c);
    }

    for (int k0 = 0; k0 < K; k0 += GBK) {
        __syncthreads();
        #pragma unroll
        for (int i = 0; i < 4; i++) {
            int idx = i * 256 + tid;
            int r = idx >> 3, c = (idx & 7) * 4;
            As[r][c+0] = f2tf(ra[i].x); As[r][c+1] = f2tf(ra[i].y);
            As[r][c+2] = f2tf(ra[i].z); As[r][c+3] = f2tf(ra[i].w);
            Bs[r][c+0] = f2tf(rb[i].x); Bs[r][c+1] = f2tf(rb[i].y);
            Bs[r][c+2] = f2tf(rb[i].z); Bs[r][c+3] = f2tf(rb[i].w);
        }
        __syncthreads();

        if (k0 + GBK < K) {
            #pragma unroll
            for (int i = 0; i < 4; i++) {
                int idx = i * 256 + tid;
                int r = idx >> 3, c = (idx & 7) * 4;
                ra[i] = *(const float4*)(Ab + (size_t)r * K + k0 + GBK + c);
                rb[i] = *(const float4*)(Wb + (size_t)r * K + k0 + GBK + c);
            }
        }

        #pragma unroll
        for (int ks = 0; ks < GBK; ks += 8) {
            unsigned af[4][4], bf[4][2];
            #pragma unroll
            for (int mi = 0; mi < 4; mi++) {
                int r = wm * 64 + mi * 16 + qr;
                af[mi][0] = As[r    ][ks + qc];
                af[mi][1] = As[r + 8][ks + qc];
                af[mi][2] = As[r    ][ks + qc + 4];
                af[mi][3] = As[r + 8][ks + qc + 4];
            }
            #pragma unroll
            for (int ni = 0; ni < 4; ni++) {
                int nb = wn * 32 + ni * 8 + qr;
                bf[ni][0] = Bs[nb][ks + qc];
                bf[ni][1] = Bs[nb][ks + qc + 4];
            }
            #pragma unroll
            for (int mi = 0; mi < 4; mi++)
                #pragma unroll
                for (int ni = 0; ni < 4; ni++)
                    mma_tf32(acc[mi][ni], af[mi], bf[ni]);
        }
    }

    // epilogue: bias + store (float2 per fragment row)
    #pragma unroll
    for (int mi = 0; mi < 4; mi++) {
        int r0 = m0 + wm * 64 + mi * 16 + qr;
        #pragma unroll
        for (int ni = 0; ni < 4; ni++) {
            int col = n0 + wn * 32 + ni * 8 + 2 * qc;
            float b0 = bias[col], b1 = bias[col + 1];
            float2 v0, v1;
            v0.x = acc[mi][ni][0] + b0; v0.y = acc[mi][ni][1] + b1;
            v1.x = acc[mi][ni][2] + b0; v1.y = acc[mi][ni][3] + b1;
            *(float2*)(C + (size_t)r0 * N + col)       = v0;
            *(float2*)(C + (size_t)(r0 + 8) * N + col) = v1;
        }
    }
}

// ---------------------------------------------------------------------------
// Tensor-core flash attention (tf32 mma), fp32 softmax.
// Block: 64 queries x 1 head x 1 batch. 4 warps, each owns 16 query rows.
// qkv layout [B,S,3D]: q at h*64, k at 1024+h*64, v at 2048+h*64.
// ---------------------------------------------------------------------------
#define ATQ 64
#define ATK 64
#define KLD (DHEAD + 4)

__global__ __launch_bounds__(128)
void flash_attn_tc(const float* __restrict__ qkv, const int* __restrict__ maskp,
                   float* __restrict__ att)
{
    __shared__ unsigned Ks[ATK][KLD];
    __shared__ unsigned Vs[ATK][KLD];

    const int tid  = threadIdx.x;
    const int wid  = tid >> 5;
    const int lane = tid & 31;
    const int qr   = lane >> 2;   // 0..7
    const int qc   = lane & 3;    // 0..3
    const int q0 = blockIdx.x * ATQ;
    const int h  = blockIdx.y;
    const int b  = blockIdx.z;
    const int mask = *maskp;
    const float* base = qkv + (size_t)b * S_LEN * 3 * DEMB;

    const int row0 = q0 + wid * 16 + qr;
    const int row1 = row0 + 8;

    // Q fragments in registers: rows row0/row1, cols ks*8 + qc (+4)
    unsigned qf[8][4];
    {
        const float* q0p = base + (size_t)row0 * (3 * DEMB) + h * DHEAD;
        const float* q1p = base + (size_t)row1 * (3 * DEMB) + h * DHEAD;
        #pragma unroll
        for (int ks = 0; ks < 8; ks++) {
            qf[ks][0] = f2tf(q0p[ks * 8 + qc]);
            qf[ks][1] = f2tf(q1p[ks * 8 + qc]);
            qf[ks][2] = f2tf(q0p[ks * 8 + qc + 4]);
            qf[ks][3] = f2tf(q1p[ks * 8 + qc + 4]);
        }
    }

    float o[8][4];
    #pragma unroll
    for (int nd = 0; nd < 8; nd++)
        #pragma unroll
        for (int c = 0; c < 4; c++) o[nd][c] = 0.0f;
    float m0r = -1e30f, m1r = -1e30f, l0 = 0.0f, l1 = 0.0f;

    const int ntiles = mask ? (q0 / ATK + 1) : (S_LEN / ATK);

    for (int t = 0; t < ntiles; t++) {
        const int k0 = t * ATK;
        __syncthreads();
        // load + convert K,V tile (64 x 64 each): 1024 float4 / 128 thr = 8 each
        #pragma unroll
        for (int i = 0; i < 8; i++) {
            int idx = i * 128 + tid;
            int r = idx >> 4, c = (idx & 15) * 4;
            const float* kp = base + (size_t)(k0 + r) * (3 * DEMB) + DEMB + h * DHEAD + c;
            float4 kv = *(const float4*)kp;
            float4 vv = *(const float4*)(kp + DEMB);
            Ks[r][c+0] = f2tf(kv.x); Ks[r][c+1] = f2tf(kv.y);
            Ks[r][c+2] = f2tf(kv.z); Ks[r][c+3] = f2tf(kv.w);
            Vs[r][c+0] = f2tf(vv.x); Vs[r][c+1] = f2tf(vv.y);
            Vs[r][c+2] = f2tf(vv.z); Vs[r][c+3] = f2tf(vv.w);
        }
        __syncthreads();

        // ----- S = Q @ K^T (16 x 64 per warp) -----
        float s[8][4];
        #pragma unroll
        for (int ni = 0; ni < 8; ni++)
            #pragma unroll
            for (int c = 0; c < 4; c++) s[ni][c] = 0.0f;

        #pragma unroll
        for (int ks = 0; ks < 8; ks++) {
            #pragma unroll
            for (int ni = 0; ni < 8; ni++) {
                unsigned bf[2];
                bf[0] = Ks[ni * 8 + qr][ks * 8 + qc];
                bf[1] = Ks[ni * 8 + qr][ks * 8 + qc + 4];
                mma_tf32(s[ni], qf[ks], bf);
            }
        }

        // scale + causal mask (only the diagonal tile needs element masking)
        const bool domask = mask && (t == ntiles - 1);
        #pragma unroll
        for (int ni = 0; ni < 8; ni++) {
            #pragma unroll
            for (int c = 0; c < 4; c++) s[ni][c] *= 0.125f;
            if (domask) {
                int col = k0 + ni * 8 + 2 * qc;
                if (col     > row0) s[ni][0] = -1e30f;
                if (col + 1 > row0) s[ni][1] = -1e30f;
                if (col     > row1) s[ni][2] = -1e30f;
                if (col + 1 > row1) s[ni][3] = -1e30f;
            }
        }

        // ----- online softmax (rows row0, row1 per thread, quad-replicated) -----
        float mx0 = -1e30f, mx1 = -1e30f;
        #pragma unroll
        for (int ni = 0; ni < 8; ni++) {
            mx0 = fmaxf(mx0, fmaxf(s[ni][0], s[ni][1]));
            mx1 = fmaxf(mx1, fmaxf(s[ni][2], s[ni][3]));
        }
        mx0 = fmaxf(mx0, __shfl_xor_sync(0xffffffffu, mx0, 1));
        mx0 = fmaxf(mx0, __shfl_xor_sync(0xffffffffu, mx0, 2));
        mx1 = fmaxf(mx1, __shfl_xor_sync(0xffffffffu, mx1, 1));
        mx1 = fmaxf(mx1, __shfl_xor_sync(0xffffffffu, mx1, 2));

        float mn0 = fmaxf(m0r, mx0), mn1 = fmaxf(m1r, mx1);
        float al0 = __expf(m0r - mn0), al1 = __expf(m1r - mn1);
        m0r = mn0; m1r = mn1;

        float rs0 = 0.0f, rs1 = 0.0f;
        #pragma unroll
        for (int ni = 0; ni < 8; ni++) {
            float p0 = __expf(s[ni][0] - mn0);
            float p1 = __expf(s[ni][1] - mn0);
            float p2 = __expf(s[ni][2] - mn1);
            float p3 = __expf(s[ni][3] - mn1);
            rs0 += p0 + p1; rs1 += p2 + p3;
            s[ni][0] = p0; s[ni][1] = p1; s[ni][2] = p2; s[ni][3] = p3;
        }
        rs0 += __shfl_xor_sync(0xffffffffu, rs0, 1);
        rs0 += __shfl_xor_sync(0xffffffffu, rs0, 2);
        rs1 += __shfl_xor_sync(0xffffffffu, rs1, 1);
        rs1 += __shfl_xor_sync(0xffffffffu, rs1, 2);
        l0 = l0 * al0 + rs0;
        l1 = l1 * al1 + rs1;
        #pragma unroll
        for (int nd = 0; nd < 8; nd++) {
            o[nd][0] *= al0; o[nd][1] *= al0;
            o[nd][2] *= al1; o[nd][3] *= al1;
        }

        // ----- O += P @ V -----
        // P is in C-fragment layout (cols 2qc,2qc+1); A-fragment needs cols qc,qc+4.
        // Within each quad: col j lives at lane (j>>1), slot (j&1).
        const int srcA = (lane & ~3) | (qc >> 1);   // col qc
        const int srcB = srcA + 2;                  // col qc+4
        const bool odd = qc & 1;
        #pragma unroll
        for (int ks = 0; ks < 8; ks++) {
            float v00 = __shfl_sync(0xffffffffu, s[ks][0], srcA);
            float v01 = __shfl_sync(0xffffffffu, s[ks][1], srcA);
            float v10 = __shfl_sync(0xffffffffu, s[ks][2], srcA);
            float v11 = __shfl_sync(0xffffffffu, s[ks][3], srcA);
            float w00 = __shfl_sync(0xffffffffu, s[ks][0], srcB);
            float w01 = __shfl_sync(0xffffffffu, s[ks][1], srcB);
            float w10 = __shfl_sync(0xffffffffu, s[ks][2], srcB);
            float w11 = __shfl_sync(0xffffffffu, s[ks][3], srcB);
            unsigned af[4];
            af[0] = f2tf(odd ? v01 : v00);
            af[1] = f2tf(odd ? v11 : v10);
            af[2] = f2tf(odd ? w01 : w00);
            af[3] = f2tf(odd ? w11 : w10);
            #pragma unroll
            for (int nd = 0; nd < 8; nd++) {
                unsigned bf[2];
                bf[0] = Vs[ks * 8 + qc    ][nd * 8 + qr];
                bf[1] = Vs[ks * 8 + qc + 4][nd * 8 + qr];
                mma_tf32(o[nd], af, bf);
            }
        }
    }

    // ----- normalize + store: att[b, row, h*64 + dh] -----
    const float inv0 = 1.0f / l0, inv1 = 1.0f / l1;
    float* op0 = att + ((size_t)b * S_LEN + row0) * DEMB + h * DHEAD;
    float* op1 = att + ((size_t)b * S_LEN + row1) * DEMB + h * DHEAD;
    #pragma unroll
    for (int nd = 0; nd < 8; nd++) {
        float2 v0, v1;
        v0.x = o[nd][0] * inv0; v0.y = o[nd][1] * inv0;
        v1.x = o[nd][2] * inv1; v1.y = o[nd][3] * inv1;
        *(float2*)(op0 + nd * 8 + 2 * qc) = v0;
        *(float2*)(op1 + nd * 8 + 2 * qc) = v1;
    }
}

// ---------------------------------------------------------------------------
extern "C" void kernel_launch(void* const* d_in, const int* in_sizes, int n_in,
                              void* d_out, int out_size)
{
    const float* x     = (const float*)d_in[0];   // [2,2048,1024]
    const float* w_in  = (const float*)d_in[1];   // [3072,1024]
    const float* b_in  = (const float*)d_in[2];   // [3072]
    const float* w_out = (const float*)d_in[3];   // [1024,1024]
    const float* b_out = (const float*)d_in[4];   // [1024]
    const int*   maskp = (const int*)d_in[5];     // apply_mask
    float* out = (float*)d_out;                   // [2,2048,1024]

    void *qkv_p = nullptr, *att_p = nullptr;
    cudaGetSymbolAddress(&qkv_p, g_qkv);
    cudaGetSymbolAddress(&att_p, g_att);
    float* qkv = (float*)qkv_p;
    float* att = (float*)att_p;

    const int M = BATCH * S_LEN;   // 4096

    // 1) QKV projection: [4096,1024] @ [3072,1024]^T + b_in
    {
        dim3 grid(3 * DEMB / GBN, M / GBM);
        gemm_tf32<<<grid, 256>>>(x, w_in, b_in, qkv, M, 3 * DEMB, DEMB);
    }

    // 2) causal flash attention (tensor cores)
    {
        dim3 grid(S_LEN / ATQ, NHEADS, BATCH);
        flash_attn_tc<<<grid, 128>>>(qkv, maskp, att);
    }

    // 3) output projection: [4096,1024] @ [1024,1024]^T + b_out
    {
        dim3 grid(DEMB / GBN, M / GBM);
        gemm_tf32<<<grid, 256>>>(att, w_out, b_out, out, M, DEMB, DEMB);
    }
}

// round 5
// speedup vs baseline: 3.6947x; 1.0083x over previous
#include <cuda_runtime.h>
#include <math.h>

#define BATCH   2
#define S_LEN   2048
#define DEMB    1024
#define NHEADS  16
#define DHEAD   64

// Scratch (allocation-free rule: __device__ globals)
__device__ float g_qkv[BATCH * S_LEN * 3 * DEMB];   // tf32-rounded [B,S,3D]
__device__ float g_att[BATCH * S_LEN * DEMB];       // tf32-rounded [B,S,D]
__device__ float g_xt  [BATCH * S_LEN * DEMB];      // tf32-rounded x
__device__ float g_wint[3 * DEMB * DEMB];           // tf32-rounded w_in
__device__ float g_wott[DEMB * DEMB];               // tf32-rounded w_out

// ---------------------------------------------------------------------------
__device__ __forceinline__ unsigned f2tf(float f) {
    unsigned u;
    asm("cvt.rna.tf32.f32 %0, %1;" : "=r"(u) : "f"(f));
    return u;
}
__device__ __forceinline__ float ex2(float x) {
    float y;
    asm("ex2.approx.f32 %0, %1;" : "=f"(y) : "f"(x));
    return y;
}
__device__ __forceinline__ void mma_tf32(float* c, const unsigned* a, const unsigned* b) {
    asm volatile(
        "mma.sync.aligned.m16n8k8.row.col.f32.tf32.tf32.f32 "
        "{%0,%1,%2,%3}, {%4,%5,%6,%7}, {%8,%9}, {%0,%1,%2,%3};"
        : "+f"(c[0]), "+f"(c[1]), "+f"(c[2]), "+f"(c[3])
        : "r"(a[0]), "r"(a[1]), "r"(a[2]), "r"(a[3]),
          "r"(b[0]), "r"(b[1]));
}

// pre-round a buffer to tf32-representable fp32 (vectorized)
__global__ void cvt_tf32_kernel(const float* __restrict__ in, float* __restrict__ out, int n4) {
    int i = blockIdx.x * blockDim.x + threadIdx.x;
    if (i < n4) {
        float4 v = ((const float4*)in)[i];
        v.x = __uint_as_float(f2tf(v.x));
        v.y = __uint_as_float(f2tf(v.y));
        v.z = __uint_as_float(f2tf(v.z));
        v.w = __uint_as_float(f2tf(v.w));
        ((float4*)out)[i] = v;
    }
}

// ---------------------------------------------------------------------------
// tf32 GEMM, fragment-order SMEM. C[M,N] = A[M,K] @ W[N,K]^T + bias[N]
// BM=BN=128, BK=32; 8 warps 2(m)x4(n); warp tile 64x32 (4x4 m16n8k8 frags).
// Inputs A, W must already be tf32-rounded fp32.
// A-frag groups (mt 0..7, kt 0..3): stride 132 words; lane holds uint4.
// B-frag groups (nt 0..15, kt 0..3): stride 66 words; lane holds uint2.
// ---------------------------------------------------------------------------
#define ASTRIDE 132
#define BSTRIDE 66

__global__ __launch_bounds__(256)
void gemm_tf32_v2(const float* __restrict__ A, const float* __restrict__ W,
                  const float* __restrict__ bias, float* __restrict__ C,
                  int M, int N, int K, int round_out)
{
    __shared__ unsigned As[32 * ASTRIDE];   // 8 mt * 4 kt groups
    __shared__ unsigned Bs[64 * BSTRIDE];   // 16 nt * 4 kt groups

    const int tid  = threadIdx.x;
    const int wid  = tid >> 5;
    const int lane = tid & 31;
    const int wm   = wid >> 2;     // 0..1
    const int wn   = wid & 3;      // 0..3
    const int qr   = lane >> 2;    // 0..7
    const int qc   = lane & 3;     // 0..3
    const int m0 = blockIdx.y * 128;
    const int n0 = blockIdx.x * 128;

    float acc[4][4][4];
    #pragma unroll
    for (int mi = 0; mi < 4; mi++)
        #pragma unroll
        for (int ni = 0; ni < 4; ni++)
            #pragma unroll
            for (int c = 0; c < 4; c++) acc[mi][ni][c] = 0.0f;

    const float* Ab = A + (size_t)m0 * K;
    const float* Wb = W + (size_t)n0 * K;

    // per-thread load geometry (4 float4 of A and of W per k-tile)
    const int lr = tid >> 3;            // row within 128 row group step 32
    const int lc = (tid & 7) * 4;       // col 0..28

    float4 ra[4], rb[4];
    #pragma unroll
    for (int i = 0; i < 4; i++) {
        int r = i * 32 + lr;
        ra[i] = *(const float4*)(Ab + (size_t)r * K + lc);
        rb[i] = *(const float4*)(Wb + (size_t)r * K + lc);
    }

    // precomputed scatter bases (depend on r,c only through fixed thread geometry)
    const int kt_st = lc >> 3;
    const int hi_st = (lc >> 2) & 1;

    for (int k0 = 0; k0 < K; k0 += 32) {
        __syncthreads();
        #pragma unroll
        for (int i = 0; i < 4; i++) {
            int r = i * 32 + lr;
            // A scatter: group (mt*4+kt), word = group*132 + (r&7)*16 + j*4 + slot
            int mt = r >> 4;
            int slotA = ((r >> 3) & 1) + 2 * hi_st;
            int baseA = (mt * 4 + kt_st) * ASTRIDE + (r & 7) * 16 + slotA;
            As[baseA +  0] = __float_as_uint(ra[i].x);
            As[baseA +  4] = __float_as_uint(ra[i].y);
            As[baseA +  8] = __float_as_uint(ra[i].z);
            As[baseA + 12] = __float_as_uint(ra[i].w);
            // B scatter: group (nt*4+kt), word = group*66 + (n&7)*8 + j*2 + hi
            int nt = r >> 3;
            int baseB = (nt * 4 + kt_st) * BSTRIDE + (r & 7) * 8 + hi_st;
            Bs[baseB + 0] = __float_as_uint(rb[i].x);
            Bs[baseB + 2] = __float_as_uint(rb[i].y);
            Bs[baseB + 4] = __float_as_uint(rb[i].z);
            Bs[baseB + 6] = __float_as_uint(rb[i].w);
        }
        __syncthreads();

        if (k0 + 32 < K) {
            #pragma unroll
            for (int i = 0; i < 4; i++) {
                int r = i * 32 + lr;
                ra[i] = *(const float4*)(Ab + (size_t)r * K + k0 + 32 + lc);
                rb[i] = *(const float4*)(Wb + (size_t)r * K + k0 + 32 + lc);
            }
        }

        #pragma unroll
        for (int kt = 0; kt < 4; kt++) {
            uint4 af[4];
            uint2 bf[4];
            #pragma unroll
            for (int mi = 0; mi < 4; mi++)
                af[mi] = *(const uint4*)&As[((wm * 4 + mi) * 4 + kt) * ASTRIDE + lane * 4];
            #pragma unroll
            for (int ni = 0; ni < 4; ni++)
                bf[ni] = *(const uint2*)&Bs[((wn * 4 + ni) * 4 + kt) * BSTRIDE + lane * 2];
            #pragma unroll
            for (int mi = 0; mi < 4; mi++)
                #pragma unroll
                for (int ni = 0; ni < 4; ni++)
                    mma_tf32(acc[mi][ni], (const unsigned*)&af[mi], (const unsigned*)&bf[ni]);
        }
    }

    // epilogue: bias + (optional tf32 rounding) + store
    #pragma unroll
    for (int mi = 0; mi < 4; mi++) {
        int r0 = m0 + wm * 64 + mi * 16 + qr;
        #pragma unroll
        for (int ni = 0; ni < 4; ni++) {
            int col = n0 + wn * 32 + ni * 8 + 2 * qc;
            float b0 = bias[col], b1 = bias[col + 1];
            float v00 = acc[mi][ni][0] + b0, v01 = acc[mi][ni][1] + b1;
            float v10 = acc[mi][ni][2] + b0, v11 = acc[mi][ni][3] + b1;
            if (round_out) {
                v00 = __uint_as_float(f2tf(v00)); v01 = __uint_as_float(f2tf(v01));
                v10 = __uint_as_float(f2tf(v10)); v11 = __uint_as_float(f2tf(v11));
            }
            *(float2*)(C + (size_t)r0 * N + col)       = make_float2(v00, v01);
            *(float2*)(C + (size_t)(r0 + 8) * N + col) = make_float2(v10, v11);
        }
    }
}

// ---------------------------------------------------------------------------
// Tensor-core flash attention, fragment-order K/V SMEM, log2-domain softmax.
// Block: 64 queries x 1 head x 1 batch; 4 warps x 16 rows.
// qkv must be tf32-rounded. Output written tf32-rounded.
// K-frags: groups (nt*8+kt), nt=keyrow/8, kt=d/8, stride 66, uint2/lane.
// V-frags: groups (kt*8+nt), kt=keyrow/8, nt=d/8, stride 66, uint2/lane.
// ---------------------------------------------------------------------------
#define ATQ 64
#define ATK 64

__global__ __launch_bounds__(128)
void flash_attn_tc2(const float* __restrict__ qkv, const int* __restrict__ maskp,
                    float* __restrict__ att)
{
    __shared__ unsigned KF[64 * BSTRIDE];
    __shared__ unsigned VF[64 * BSTRIDE];

    const int tid  = threadIdx.x;
    const int wid  = tid >> 5;
    const int lane = tid & 31;
    const int qr   = lane >> 2;
    const int qc   = lane & 3;
    const int q0 = blockIdx.x * ATQ;
    const int h  = blockIdx.y;
    const int b  = blockIdx.z;
    const int mask = *maskp;
    const float* base = qkv + (size_t)b * S_LEN * 3 * DEMB;

    const int row0 = q0 + wid * 16 + qr;
    const int row1 = row0 + 8;

    // Q fragments (already tf32-rounded; plain loads)
    unsigned qf[8][4];
    {
        const float* q0p = base + (size_t)row0 * (3 * DEMB) + h * DHEAD;
        const float* q1p = base + (size_t)row1 * (3 * DEMB) + h * DHEAD;
        #pragma unroll
        for (int ks = 0; ks < 8; ks++) {
            qf[ks][0] = __float_as_uint(q0p[ks * 8 + qc]);
            qf[ks][1] = __float_as_uint(q1p[ks * 8 + qc]);
            qf[ks][2] = __float_as_uint(q0p[ks * 8 + qc + 4]);
            qf[ks][3] = __float_as_uint(q1p[ks * 8 + qc + 4]);
        }
    }

    float o[8][4];
    #pragma unroll
    for (int nd = 0; nd < 8; nd++)
        #pragma unroll
        for (int c = 0; c < 4; c++) o[nd][c] = 0.0f;
    float m0r = -1e30f, m1r = -1e30f, l0 = 0.0f, l1 = 0.0f;

    const float SCL = 0.125f * 1.4426950408889634f;   // /sqrt(64) * log2(e)
    const int ntiles = mask ? (q0 / ATK + 1) : (S_LEN / ATK);

    // loader geometry: idx = i*128+tid; r = idx>>4 (0..63); c = (idx&15)*4
    const int lrr = tid >> 4;          // row step 8
    const int lcc = (tid & 15) * 4;    // col 0..60
    const int kt_c = lcc >> 3;
    const int hi_c = (lcc >> 2) & 1;

    for (int t = 0; t < ntiles; t++) {
        const int k0 = t * ATK;
        __syncthreads();
        #pragma unroll
        for (int i = 0; i < 8; i++) {
            int r = i * 8 + lrr;
            const float* kp = base + (size_t)(k0 + r) * (3 * DEMB) + DEMB + h * DHEAD + lcc;
            float4 kv = *(const float4*)kp;
            float4 vv = *(const float4*)(kp + DEMB);
            // K scatter: word = (nt*8+kt)*66 + (r&7)*8 + j*2 + hi
            {
                int baseK = ((r >> 3) * 8 + kt_c) * BSTRIDE + (r & 7) * 8 + hi_c;
                KF[baseK + 0] = __float_as_uint(kv.x);
                KF[baseK + 2] = __float_as_uint(kv.y);
                KF[baseK + 4] = __float_as_uint(kv.z);
                KF[baseK + 6] = __float_as_uint(kv.w);
            }
            // V scatter: word = (kt*8+nt)*66 + ((c&7)+j)*8 + (r&3)*2 + ((r&4)>>2)
            {
                int baseV = ((r >> 3) * 8 + kt_c) * BSTRIDE + (lcc & 7) * 8
                          + (r & 3) * 2 + ((r & 4) >> 2);
                VF[baseV +  0] = __float_as_uint(vv.x);
                VF[baseV +  8] = __float_as_uint(vv.y);
                VF[baseV + 16] = __float_as_uint(vv.z);
                VF[baseV + 24] = __float_as_uint(vv.w);
            }
        }
        __syncthreads();

        // ----- S = Q @ K^T -----
        float s[8][4];
        #pragma unroll
        for (int ni = 0; ni < 8; ni++)
            #pragma unroll
            for (int c = 0; c < 4; c++) s[ni][c] = 0.0f;

        #pragma unroll
        for (int ks = 0; ks < 8; ks++) {
            #pragma unroll
            for (int ni = 0; ni < 8; ni++) {
                uint2 bf = *(const uint2*)&KF[(ni * 8 + ks) * BSTRIDE + lane * 2];
                mma_tf32(s[ni], qf[ks], (const unsigned*)&bf);
            }
        }

        // scale into log2 domain + causal mask on diagonal tile
        const bool domask = mask && (t == ntiles - 1);
        #pragma unroll
        for (int ni = 0; ni < 8; ni++) {
            #pragma unroll
            for (int c = 0; c < 4; c++) s[ni][c] *= SCL;
            if (domask) {
                int col = k0 + ni * 8 + 2 * qc;
                if (col     > row0) s[ni][0] = -1e30f;
                if (col + 1 > row0) s[ni][1] = -1e30f;
                if (col     > row1) s[ni][2] = -1e30f;
                if (col + 1 > row1) s[ni][3] = -1e30f;
            }
        }

        // ----- online softmax (log2 domain) -----
        float mx0 = -1e30f, mx1 = -1e30f;
        #pragma unroll
        for (int ni = 0; ni < 8; ni++) {
            mx0 = fmaxf(mx0, fmaxf(s[ni][0], s[ni][1]));
            mx1 = fmaxf(mx1, fmaxf(s[ni][2], s[ni][3]));
        }
        mx0 = fmaxf(mx0, __shfl_xor_sync(0xffffffffu, mx0, 1));
        mx0 = fmaxf(mx0, __shfl_xor_sync(0xffffffffu, mx0, 2));
        mx1 = fmaxf(mx1, __shfl_xor_sync(0xffffffffu, mx1, 1));
        mx1 = fmaxf(mx1, __shfl_xor_sync(0xffffffffu, mx1, 2));

        float mn0 = fmaxf(m0r, mx0), mn1 = fmaxf(m1r, mx1);
        float al0 = ex2(m0r - mn0), al1 = ex2(m1r - mn1);
        m0r = mn0; m1r = mn1;

        float rs0 = 0.0f, rs1 = 0.0f;
        #pragma unroll
        for (int ni = 0; ni < 8; ni++) {
            float p0 = ex2(s[ni][0] - mn0);
            float p1 = ex2(s[ni][1] - mn0);
            float p2 = ex2(s[ni][2] - mn1);
            float p3 = ex2(s[ni][3] - mn1);
            rs0 += p0 + p1; rs1 += p2 + p3;
            s[ni][0] = p0; s[ni][1] = p1; s[ni][2] = p2; s[ni][3] = p3;
        }
        rs0 += __shfl_xor_sync(0xffffffffu, rs0, 1);
        rs0 += __shfl_xor_sync(0xffffffffu, rs0, 2);
        rs1 += __shfl_xor_sync(0xffffffffu, rs1, 1);
        rs1 += __shfl_xor_sync(0xffffffffu, rs1, 2);
        l0 = l0 * al0 + rs0;
        l1 = l1 * al1 + rs1;
        #pragma unroll
        for (int nd = 0; nd < 8; nd++) {
            o[nd][0] *= al0; o[nd][1] *= al0;
            o[nd][2] *= al1; o[nd][3] *= al1;
        }

        // ----- O += P @ V (P C-layout -> A-layout via quad shuffles) -----
        const int srcA = (lane & ~3) | (qc >> 1);
        const int srcB = srcA + 2;
        const bool odd = qc & 1;
        #pragma unroll
        for (int ks = 0; ks < 8; ks++) {
            float v00 = __shfl_sync(0xffffffffu, s[ks][0], srcA);
            float v01 = __shfl_sync(0xffffffffu, s[ks][1], srcA);
            float v10 = __shfl_sync(0xffffffffu, s[ks][2], srcA);
            float v11 = __shfl_sync(0xffffffffu, s[ks][3], srcA);
            float w00 = __shfl_sync(0xffffffffu, s[ks][0], srcB);
            float w01 = __shfl_sync(0xffffffffu, s[ks][1], srcB);
            float w10 = __shfl_sync(0xffffffffu, s[ks][2], srcB);
            float w11 = __shfl_sync(0xffffffffu, s[ks][3], srcB);
            unsigned af[4];
            af[0] = f2tf(odd ? v01 : v00);
            af[1] = f2tf(odd ? v11 : v10);
            af[2] = f2tf(odd ? w01 : w00);
            af[3] = f2tf(odd ? w11 : w10);
            #pragma unroll
            for (int nd = 0; nd < 8; nd++) {
                uint2 bf = *(const uint2*)&VF[(ks * 8 + nd) * BSTRIDE + lane * 2];
                mma_tf32(o[nd], af, (const unsigned*)&bf);
            }
        }
    }

    // ----- normalize + tf32-round + store -----
    const float inv0 = 1.0f / l0, inv1 = 1.0f / l1;
    float* op0 = att + ((size_t)b * S_LEN + row0) * DEMB + h * DHEAD;
    float* op1 = att + ((size_t)b * S_LEN + row1) * DEMB + h * DHEAD;
    #pragma unroll
    for (int nd = 0; nd < 8; nd++) {
        float2 v0, v1;
        v0.x = __uint_as_float(f2tf(o[nd][0] * inv0));
        v0.y = __uint_as_float(f2tf(o[nd][1] * inv0));
        v1.x = __uint_as_float(f2tf(o[nd][2] * inv1));
        v1.y = __uint_as_float(f2tf(o[nd][3] * inv1));
        *(float2*)(op0 + nd * 8 + 2 * qc) = v0;
        *(float2*)(op1 + nd * 8 + 2 * qc) = v1;
    }
}

// ---------------------------------------------------------------------------
extern "C" void kernel_launch(void* const* d_in, const int* in_sizes, int n_in,
                              void* d_out, int out_size)
{
    const float* x     = (const float*)d_in[0];
    const float* w_in  = (const float*)d_in[1];
    const float* b_in  = (const float*)d_in[2];
    const float* w_out = (const float*)d_in[3];
    const float* b_out = (const float*)d_in[4];
    const int*   maskp = (const int*)d_in[5];
    float* out = (float*)d_out;

    void *qkv_p, *att_p, *xt_p, *wint_p, *wott_p;
    cudaGetSymbolAddress(&qkv_p, g_qkv);
    cudaGetSymbolAddress(&att_p, g_att);
    cudaGetSymbolAddress(&xt_p, g_xt);
    cudaGetSymbolAddress(&wint_p, g_wint);
    cudaGetSymbolAddress(&wott_p, g_wott);
    float* qkv  = (float*)qkv_p;
    float* att  = (float*)att_p;
    float* xt   = (float*)xt_p;
    float* wint = (float*)wint_p;
    float* wott = (float*)wott_p;

    const int M = BATCH * S_LEN;   // 4096

    // 0) pre-round inputs to tf32
    {
        int n4;
        n4 = (M * DEMB) / 4;
        cvt_tf32_kernel<<<(n4 + 255) / 256, 256>>>(x, xt, n4);
        n4 = (3 * DEMB * DEMB) / 4;
        cvt_tf32_kernel<<<(n4 + 255) / 256, 256>>>(w_in, wint, n4);
        n4 = (DEMB * DEMB) / 4;
        cvt_tf32_kernel<<<(n4 + 255) / 256, 256>>>(w_out, wott, n4);
    }

    // 1) QKV projection (epilogue rounds to tf32)
    {
        dim3 grid(3 * DEMB / 128, M / 128);
        gemm_tf32_v2<<<grid, 256>>>(xt, wint, b_in, qkv, M, 3 * DEMB, DEMB, 1);
    }

    // 2) causal flash attention (tensor cores; writes tf32-rounded att)
    {
        dim3 grid(S_LEN / ATQ, NHEADS, BATCH);
        flash_attn_tc2<<<grid, 128>>>(qkv, maskp, att);
    }

    // 3) output projection (full fp32 out)
    {
        dim3 grid(DEMB / 128, M / 128);
        gemm_tf32_v2<<<grid, 256>>>(att, wott, b_out, out, M, DEMB, DEMB, 0);
    }
}

// round 8
// speedup vs baseline: 4.0786x; 1.1039x over previous
#include <cuda_runtime.h>
#include <stdint.h>
#include <math.h>

#define S_LEN   2048
#define DEMB    1024
#define MTOT    4096            // BATCH * S_LEN
#define NHEADS  16
#define DHEAD   64

// ---------------- device scratch (allocation-free rule) ----------------
__device__ float    g_qkv [MTOT * 3 * DEMB];   // tf32-rounded, natural [B,S,3D]
__device__ float    g_att [MTOT * DEMB];       // attention out, natural
__device__ uint32_t g_xf  [MTOT * DEMB];       // x in A-frag order (tf32)
__device__ uint32_t g_attf[MTOT * DEMB];       // att in A-frag order (tf32)
__device__ uint32_t g_wif [3 * DEMB * DEMB];   // w_in in B-frag order
__device__ uint32_t g_wof [DEMB * DEMB];       // w_out in B-frag order

// ---------------- helpers ----------------
__device__ __forceinline__ uint32_t f2tf(float f) {
    uint32_t u; asm("cvt.rna.tf32.f32 %0, %1;" : "=r"(u) : "f"(f)); return u;
}
__device__ __forceinline__ float ex2(float x) {
    float y; asm("ex2.approx.f32 %0, %1;" : "=f"(y) : "f"(x)); return y;
}
__device__ __forceinline__ void mma_tf32(float* c, const uint32_t* a, const uint32_t* b) {
    asm volatile(
        "mma.sync.aligned.m16n8k8.row.col.f32.tf32.tf32.f32 "
        "{%0,%1,%2,%3}, {%4,%5,%6,%7}, {%8,%9}, {%0,%1,%2,%3};"
        : "+f"(c[0]), "+f"(c[1]), "+f"(c[2]), "+f"(c[3])
        : "r"(a[0]), "r"(a[1]), "r"(a[2]), "r"(a[3]), "r"(b[0]), "r"(b[1]));
}
__device__ __forceinline__ uint32_t smem_u32(const void* p) {
    uint32_t a;
    asm("{ .reg .u64 t; cvta.to.shared.u64 t, %1; cvt.u32.u64 %0, t; }" : "=r"(a) : "l"(p));
    return a;
}
__device__ __forceinline__ void cpa16(uint32_t dst, const void* src) {
    asm volatile("cp.async.cg.shared.global [%0], [%1], 16;" :: "r"(dst), "l"(src) : "memory");
}

// ---------------------------------------------------------------------------
// Repack kernels: natural fp32 -> tf32-rounded fragment-ordered uint32.
// A-frag layout [M x K]: tile (tm,tk) of 16x8; word gid = ((tm*K8+tk)*32+lane)*4+j
//   j0=A[tm16+qr][tk8+qc], j1=A[+8][qc], j2=A[qr][qc+4], j3=A[+8][qc+4]
// B-frag layout [N x K]: tile (tn,tk) of 8x8; uint2 gid = (tn*K8+tk)*32+lane
//   j0=W[tn8+qr][tk8+qc], j1=W[tn8+qr][tk8+qc+4]
// ---------------------------------------------------------------------------
__global__ void repack_A(const float* __restrict__ in, uint32_t* __restrict__ out, int K) {
    int gid  = blockIdx.x * 256 + threadIdx.x;      // one uint4 per thread
    int lane = gid & 31, tile = gid >> 5;
    int k8 = K >> 3;
    int tk = tile % k8, tm = tile / k8;
    int qr = lane >> 2, qc = lane & 3;
    const float* p = in + (size_t)(tm * 16 + qr) * K + tk * 8 + qc;
    uint4 u;
    u.x = f2tf(p[0]);
    u.y = f2tf(p[(size_t)8 * K]);
    u.z = f2tf(p[4]);
    u.w = f2tf(p[(size_t)8 * K + 4]);
    ((uint4*)out)[gid] = u;
}

__global__ void repack_B(const float* __restrict__ in, uint32_t* __restrict__ out, int K) {
    int gid  = blockIdx.x * 256 + threadIdx.x;      // one uint2 per thread
    int lane = gid & 31, tile = gid >> 5;
    int k8 = K >> 3;
    int tk = tile % k8, tn = tile / k8;
    int qr = lane >> 2, qc = lane & 3;
    const float* p = in + (size_t)(tn * 8 + qr) * K + tk * 8 + qc;
    uint2 u;
    u.x = f2tf(p[0]);
    u.y = f2tf(p[4]);
    ((uint2*)out)[gid] = u;
}

// ---------------------------------------------------------------------------
// Fragment-ordered tf32 GEMM: C[M,N] = A @ W^T + bias.
// 128x128 CTA tile, BK=32, 2-stage cp.async double buffer, 1 barrier/ktile.
// 8 warps: wm(2) x wn(4); warp tile 64x32 = 4x4 m16n8k8 frags.
// smem/stage: A 16KB (32 tiles x 512B) + B 16KB (64 tiles x 256B).
// ---------------------------------------------------------------------------
#define GSMEM 65536

__device__ __forceinline__ void gemm_copy_chunk(
    uint32_t sb, int stage, const char* Ab, const char* Bb,
    int tm0, int tn0, int k8, int c, int tid)
{
    uint32_t dA = sb + stage * 32768;
    uint32_t dB = dA + 16384;
    int tkc = c * 4;
    #pragma unroll
    for (int i = 0; i < 4; i++) {
        int seg = i * 256 + tid;
        int t = seg >> 5, off = (seg & 31) * 16;
        cpa16(dA + t * 512 + off,
              Ab + (size_t)((tm0 + (t >> 2)) * k8 + tkc + (t & 3)) * 512 + off);
    }
    #pragma unroll
    for (int i = 0; i < 4; i++) {
        int seg = i * 256 + tid;
        int t = seg >> 4, off = (seg & 15) * 16;
        cpa16(dB + t * 256 + off,
              Bb + (size_t)((tn0 + (t >> 2)) * k8 + tkc + (t & 3)) * 256 + off);
    }
    asm volatile("cp.async.commit_group;" ::: "memory");
}

__global__ __launch_bounds__(256)
void gemm_frag(const uint32_t* __restrict__ Af, const uint32_t* __restrict__ Bf,
               const float* __restrict__ bias, float* __restrict__ C,
               int N, int K, int round_out)
{
    extern __shared__ uint32_t smraw[];
    uint32_t sb = smem_u32(smraw);

    const int tid = threadIdx.x, wid = tid >> 5, lane = tid & 31;
    const int wm = wid >> 2, wn = wid & 3;
    const int qr = lane >> 2, qc = lane & 3;
    const int k8 = K >> 3;
    const int tm0 = blockIdx.y * 8, tn0 = blockIdx.x * 16;
    const int m0 = blockIdx.y * 128, n0 = blockIdx.x * 128;

    float acc[4][4][4];
    #pragma unroll
    for (int mi = 0; mi < 4; mi++)
        #pragma unroll
        for (int ni = 0; ni < 4; ni++)
            #pragma unroll
            for (int c = 0; c < 4; c++) acc[mi][ni][c] = 0.0f;

    const char* Ab = (const char*)Af;
    const char* Bb = (const char*)Bf;

    const int NC = K >> 5;   // 32
    gemm_copy_chunk(sb, 0, Ab, Bb, tm0, tn0, k8, 0, tid);

    for (int c = 0; c < NC; c++) {
        asm volatile("cp.async.wait_group 0;" ::: "memory");
        __syncthreads();
        if (c + 1 < NC)
            gemm_copy_chunk(sb, (c + 1) & 1, Ab, Bb, tm0, tn0, k8, c + 1, tid);

        uint32_t aB = sb + (c & 1) * 32768;
        uint32_t bB = aB + 16384;
        #pragma unroll
        for (int kt = 0; kt < 4; kt++) {
            uint4 af[4]; uint2 bf[4];
            #pragma unroll
            for (int mi = 0; mi < 4; mi++) {
                uint32_t addr = aB + (((wm * 4 + mi) * 4 + kt) * 512) + lane * 16;
                asm volatile("ld.shared.v4.u32 {%0,%1,%2,%3}, [%4];"
                    : "=r"(af[mi].x), "=r"(af[mi].y), "=r"(af[mi].z), "=r"(af[mi].w)
                    : "r"(addr));
            }
            #pragma unroll
            for (int ni = 0; ni < 4; ni++) {
                uint32_t addr = bB + (((wn * 4 + ni) * 4 + kt) * 256) + lane * 8;
                asm volatile("ld.shared.v2.u32 {%0,%1}, [%2];"
                    : "=r"(bf[ni].x), "=r"(bf[ni].y) : "r"(addr));
            }
            #pragma unroll
            for (int mi = 0; mi < 4; mi++)
                #pragma unroll
                for (int ni = 0; ni < 4; ni++)
                    mma_tf32(acc[mi][ni], &af[mi].x, &bf[ni].x);
        }
    }

    // epilogue: bias + optional tf32 rounding + store
    #pragma unroll
    for (int mi = 0; mi < 4; mi++) {
        int r0 = m0 + wm * 64 + mi * 16 + qr;
        #pragma unroll
        for (int ni = 0; ni < 4; ni++) {
            int col = n0 + wn * 32 + ni * 8 + 2 * qc;
            float b0 = bias[col], b1 = bias[col + 1];
            float v00 = acc[mi][ni][0] + b0, v01 = acc[mi][ni][1] + b1;
            float v10 = acc[mi][ni][2] + b0, v11 = acc[mi][ni][3] + b1;
            if (round_out) {
                v00 = __uint_as_float(f2tf(v00)); v01 = __uint_as_float(f2tf(v01));
                v10 = __uint_as_float(f2tf(v10)); v11 = __uint_as_float(f2tf(v11));
            }
            *(float2*)(C + (size_t)r0 * N + col)       = make_float2(v00, v01);
            *(float2*)(C + (size_t)(r0 + 8) * N + col) = make_float2(v10, v11);
        }
    }
}

// ---------------------------------------------------------------------------
// Tensor-core flash attention (tf32 mma.sync), fragment-order K/V SMEM,
// log2 softmax. 128 queries x 1 head x 1 batch per block; 8 warps x 16 rows.
// qkv is tf32-rounded (by GEMM1 epilogue). Register-prefetch of next tile.
// ---------------------------------------------------------------------------
#define BSTRIDE 66

__global__ __launch_bounds__(256)
void flash_attn(const float* __restrict__ qkv, const int* __restrict__ maskp,
                float* __restrict__ att)
{
    __shared__ uint32_t KF[64 * BSTRIDE];
    __shared__ uint32_t VF[64 * BSTRIDE];

    const int tid  = threadIdx.x;
    const int wid  = tid >> 5;
    const int lane = tid & 31;
    const int qr   = lane >> 2;
    const int qc   = lane & 3;
    const int qblk = gridDim.x - 1 - blockIdx.x;     // heavy blocks first
    const int q0 = qblk * 128;
    const int h  = blockIdx.y;
    const int b  = blockIdx.z;
    const int mask = *maskp;
    const float* base = qkv + (size_t)b * S_LEN * 3 * DEMB;

    const int row0 = q0 + wid * 16 + qr;
    const int row1 = row0 + 8;
    const int wmax = q0 + wid * 16 + 15;

    // Q fragments (already tf32-rounded)
    uint32_t qf[8][4];
    {
        const float* q0p = base + (size_t)row0 * (3 * DEMB) + h * DHEAD;
        const float* q1p = base + (size_t)row1 * (3 * DEMB) + h * DHEAD;
        #pragma unroll
        for (int ks = 0; ks < 8; ks++) {
            qf[ks][0] = __float_as_uint(q0p[ks * 8 + qc]);
            qf[ks][1] = __float_as_uint(q1p[ks * 8 + qc]);
            qf[ks][2] = __float_as_uint(q0p[ks * 8 + qc + 4]);
            qf[ks][3] = __float_as_uint(q1p[ks * 8 + qc + 4]);
        }
    }

    float o[8][4];
    #pragma unroll
    for (int nd = 0; nd < 8; nd++)
        #pragma unroll
        for (int c = 0; c < 4; c++) o[nd][c] = 0.0f;
    float m0r = -1e30f, m1r = -1e30f, l0 = 0.0f, l1 = 0.0f;

    const float SCL = 0.125f * 1.4426950408889634f;
    const int ntiles = mask ? (q0 / 64 + 2) : (S_LEN / 64);

    const int lrb = tid >> 4;            // 0..15
    const int c4  = (tid & 15) * 4;      // 0..60
    const int kt_c = c4 >> 3;
    const int hi_c = (c4 >> 2) & 1;

    // prefetch tile 0
    float4 kreg[4], vreg[4];
    #pragma unroll
    for (int i = 0; i < 4; i++) {
        int r = i * 16 + lrb;
        const float* kp = base + (size_t)r * (3 * DEMB) + DEMB + h * DHEAD + c4;
        kreg[i] = *(const float4*)kp;
        vreg[i] = *(const float4*)(kp + DEMB);
    }

    for (int t = 0; t < ntiles; t++) {
        const int k0 = t * 64;
        __syncthreads();
        // scatter prefetched tile into fragment-order SMEM
        #pragma unroll
        for (int i = 0; i < 4; i++) {
            int r = i * 16 + lrb;
            int bK = ((r >> 3) * 8 + kt_c) * BSTRIDE + (r & 7) * 8 + hi_c;
            KF[bK + 0] = __float_as_uint(kreg[i].x);
            KF[bK + 2] = __float_as_uint(kreg[i].y);
            KF[bK + 4] = __float_as_uint(kreg[i].z);
            KF[bK + 6] = __float_as_uint(kreg[i].w);
            int bV = ((r >> 3) * 8 + kt_c) * BSTRIDE + (c4 & 7) * 8
                   + (r & 3) * 2 + ((r & 4) >> 2);
            VF[bV +  0] = __float_as_uint(vreg[i].x);
            VF[bV +  8] = __float_as_uint(vreg[i].y);
            VF[bV + 16] = __float_as_uint(vreg[i].z);
            VF[bV + 24] = __float_as_uint(vreg[i].w);
        }
        __syncthreads();
        // prefetch next tile (overlaps with compute below)
        if (t + 1 < ntiles) {
            int kn = (t + 1) * 64;
            #pragma unroll
            for (int i = 0; i < 4; i++) {
                int r = i * 16 + lrb;
                const float* kp = base + (size_t)(kn + r) * (3 * DEMB) + DEMB + h * DHEAD + c4;
                kreg[i] = *(const float4*)kp;
                vreg[i] = *(const float4*)(kp + DEMB);
            }
        }
        if (mask && k0 > wmax) continue;   // fully-masked tile for this warp

        // ----- S = Q @ K^T -----
        float s[8][4];
        #pragma unroll
        for (int ni = 0; ni < 8; ni++)
            #pragma unroll
            for (int c = 0; c < 4; c++) s[ni][c] = 0.0f;
        #pragma unroll
        for (int ks = 0; ks < 8; ks++) {
            #pragma unroll
            for (int ni = 0; ni < 8; ni++) {
                uint2 bf = *(const uint2*)&KF[(ni * 8 + ks) * BSTRIDE + lane * 2];
                mma_tf32(s[ni], qf[ks], &bf.x);
            }
        }

        const bool domask = mask && (k0 + 63 > row0);
        #pragma unroll
        for (int ni = 0; ni < 8; ni++) {
            #pragma unroll
            for (int c = 0; c < 4; c++) s[ni][c] *= SCL;
            if (domask) {
                int col = k0 + ni * 8 + 2 * qc;
                if (col     > row0) s[ni][0] = -1e30f;
                if (col + 1 > row0) s[ni][1] = -1e30f;
                if (col     > row1) s[ni][2] = -1e30f;
                if (col + 1 > row1) s[ni][3] = -1e30f;
            }
        }

        // ----- online softmax (log2 domain) -----
        float mx0 = -1e30f, mx1 = -1e30f;
        #pragma unroll
        for (int ni = 0; ni < 8; ni++) {
            mx0 = fmaxf(mx0, fmaxf(s[ni][0], s[ni][1]));
            mx1 = fmaxf(mx1, fmaxf(s[ni][2], s[ni][3]));
        }
        mx0 = fmaxf(mx0, __shfl_xor_sync(0xffffffffu, mx0, 1));
        mx0 = fmaxf(mx0, __shfl_xor_sync(0xffffffffu, mx0, 2));
        mx1 = fmaxf(mx1, __shfl_xor_sync(0xffffffffu, mx1, 1));
        mx1 = fmaxf(mx1, __shfl_xor_sync(0xffffffffu, mx1, 2));

        float mn0 = fmaxf(m0r, mx0), mn1 = fmaxf(m1r, mx1);
        float al0 = ex2(m0r - mn0), al1 = ex2(m1r - mn1);
        m0r = mn0; m1r = mn1;

        float rs0 = 0.0f, rs1 = 0.0f;
        #pragma unroll
        for (int ni = 0; ni < 8; ni++) {
            float p0 = ex2(s[ni][0] - mn0);
            float p1 = ex2(s[ni][1] - mn0);
            float p2 = ex2(s[ni][2] - mn1);
            float p3 = ex2(s[ni][3] - mn1);
            rs0 += p0 + p1; rs1 += p2 + p3;
            s[ni][0] = p0; s[ni][1] = p1; s[ni][2] = p2; s[ni][3] = p3;
        }
        rs0 += __shfl_xor_sync(0xffffffffu, rs0, 1);
        rs0 += __shfl_xor_sync(0xffffffffu, rs0, 2);
        rs1 += __shfl_xor_sync(0xffffffffu, rs1, 1);
        rs1 += __shfl_xor_sync(0xffffffffu, rs1, 2);
        l0 = l0 * al0 + rs0;
        l1 = l1 * al1 + rs1;
        #pragma unroll
        for (int nd = 0; nd < 8; nd++) {
            o[nd][0] *= al0; o[nd][1] *= al0;
            o[nd][2] *= al1; o[nd][3] *= al1;
        }

        // ----- O += P @ V (P C-layout -> A-layout via quad shuffles) -----
        const int srcA = (lane & ~3) | (qc >> 1);
        const int srcB = srcA + 2;
        const bool odd = qc & 1;
        #pragma unroll
        for (int ks = 0; ks < 8; ks++) {
            float v00 = __shfl_sync(0xffffffffu, s[ks][0], srcA);
            float v01 = __shfl_sync(0xffffffffu, s[ks][1], srcA);
            float v10 = __shfl_sync(0xffffffffu, s[ks][2], srcA);
            float v11 = __shfl_sync(0xffffffffu, s[ks][3], srcA);
            float w00 = __shfl_sync(0xffffffffu, s[ks][0], srcB);
            float w01 = __shfl_sync(0xffffffffu, s[ks][1], srcB);
            float w10 = __shfl_sync(0xffffffffu, s[ks][2], srcB);
            float w11 = __shfl_sync(0xffffffffu, s[ks][3], srcB);
            uint32_t af[4];
            af[0] = f2tf(odd ? v01 : v00);
            af[1] = f2tf(odd ? v11 : v10);
            af[2] = f2tf(odd ? w01 : w00);
            af[3] = f2tf(odd ? w11 : w10);
            #pragma unroll
            for (int nd = 0; nd < 8; nd++) {
                uint2 bf = *(const uint2*)&VF[(ks * 8 + nd) * BSTRIDE + lane * 2];
                mma_tf32(o[nd], af, &bf.x);
            }
        }
    }

    // ----- normalize + store (natural layout; repack rounds later) -----
    const float inv0 = 1.0f / l0, inv1 = 1.0f / l1;
    float* op0 = att + ((size_t)b * S_LEN + row0) * DEMB + h * DHEAD;
    float* op1 = att + ((size_t)b * S_LEN + row1) * DEMB + h * DHEAD;
    #pragma unroll
    for (int nd = 0; nd < 8; nd++) {
        *(float2*)(op0 + nd * 8 + 2 * qc) = make_float2(o[nd][0] * inv0, o[nd][1] * inv0);
        *(float2*)(op1 + nd * 8 + 2 * qc) = make_float2(o[nd][2] * inv1, o[nd][3] * inv1);
    }
}

// ---------------------------------------------------------------------------
extern "C" void kernel_launch(void* const* d_in, const int* in_sizes, int n_in,
                              void* d_out, int out_size)
{
    const float* x     = (const float*)d_in[0];
    const float* w_in  = (const float*)d_in[1];
    const float* b_in  = (const float*)d_in[2];
    const float* w_out = (const float*)d_in[3];
    const float* b_out = (const float*)d_in[4];
    const int*   maskp = (const int*)d_in[5];
    float* out = (float*)d_out;

    void *qkv_p, *att_p, *xf_p, *attf_p, *wif_p, *wof_p;
    cudaGetSymbolAddress(&qkv_p, g_qkv);
    cudaGetSymbolAddress(&att_p, g_att);
    cudaGetSymbolAddress(&xf_p, g_xf);
    cudaGetSymbolAddress(&attf_p, g_attf);
    cudaGetSymbolAddress(&wif_p, g_wif);
    cudaGetSymbolAddress(&wof_p, g_wof);
    float*    qkv  = (float*)qkv_p;
    float*    att  = (float*)att_p;
    uint32_t* xf   = (uint32_t*)xf_p;
    uint32_t* attf = (uint32_t*)attf_p;
    uint32_t* wif  = (uint32_t*)wif_p;
    uint32_t* wof  = (uint32_t*)wof_p;

    cudaFuncSetAttribute(gemm_frag, cudaFuncAttributeMaxDynamicSharedMemorySize, GSMEM);

    // 0) repack inputs into fragment order (tf32-rounded)
    repack_A<<<MTOT * DEMB / 4 / 256, 256>>>(x, xf, DEMB);
    repack_B<<<3 * DEMB * DEMB / 2 / 256, 256>>>(w_in, wif, DEMB);
    repack_B<<<DEMB * DEMB / 2 / 256, 256>>>(w_out, wof, DEMB);

    // 1) QKV projection (epilogue rounds to tf32)
    gemm_frag<<<dim3(3 * DEMB / 128, MTOT / 128), 256, GSMEM>>>(
        xf, wif, b_in, qkv, 3 * DEMB, DEMB, 1);

    // 2) causal flash attention
    flash_attn<<<dim3(S_LEN / 128, NHEADS, 2), 256>>>(qkv, maskp, att);

    // 3) repack attention output into A-frag order
    repack_A<<<MTOT * DEMB / 4 / 256, 256>>>(att, attf, DEMB);

    // 4) output projection (full fp32 out)
    gemm_frag<<<dim3(DEMB / 128, MTOT / 128), 256, GSMEM>>>(
        attf, wof, b_out, out, DEMB, DEMB, 0);
}

// round 9
// speedup vs baseline: 5.1891x; 1.2723x over previous
#include <cuda_runtime.h>
#include <cuda_fp16.h>
#include <stdint.h>
#include <math.h>

#define S_LEN   2048
#define DEMB    1024
#define MTOT    4096            // BATCH * S_LEN
#define NHEADS  16
#define DHEAD   64

// ---------------- device scratch (allocation-free rule) ----------------
__device__ float    g_qkv [MTOT * 3 * DEMB];   // fp32 [B,S,3D]
__device__ float    g_att [MTOT * DEMB];       // attention out, natural
__device__ uint32_t g_xf  [MTOT * DEMB];       // x in A-frag order (tf32)
__device__ uint32_t g_attf[MTOT * DEMB];       // att in A-frag order (tf32)
__device__ uint32_t g_wif [3 * DEMB * DEMB];   // w_in in B-frag order
__device__ uint32_t g_wof [DEMB * DEMB];       // w_out in B-frag order

// ---------------- helpers ----------------
__device__ __forceinline__ uint32_t f2tf(float f) {
    uint32_t u; asm("cvt.rna.tf32.f32 %0, %1;" : "=r"(u) : "f"(f)); return u;
}
__device__ __forceinline__ float ex2(float x) {
    float y; asm("ex2.approx.f32 %0, %1;" : "=f"(y) : "f"(x)); return y;
}
__device__ __forceinline__ void mma_tf32(float* c, const uint32_t* a, const uint32_t* b) {
    asm volatile(
        "mma.sync.aligned.m16n8k8.row.col.f32.tf32.tf32.f32 "
        "{%0,%1,%2,%3}, {%4,%5,%6,%7}, {%8,%9}, {%0,%1,%2,%3};"
        : "+f"(c[0]), "+f"(c[1]), "+f"(c[2]), "+f"(c[3])
        : "r"(a[0]), "r"(a[1]), "r"(a[2]), "r"(a[3]), "r"(b[0]), "r"(b[1]));
}
__device__ __forceinline__ void mma_f16(float* c, const uint32_t* a, const uint32_t* b) {
    asm volatile(
        "mma.sync.aligned.m16n8k16.row.col.f32.f16.f16.f32 "
        "{%0,%1,%2,%3}, {%4,%5,%6,%7}, {%8,%9}, {%0,%1,%2,%3};"
        : "+f"(c[0]), "+f"(c[1]), "+f"(c[2]), "+f"(c[3])
        : "r"(a[0]), "r"(a[1]), "r"(a[2]), "r"(a[3]), "r"(b[0]), "r"(b[1]));
}
__device__ __forceinline__ uint32_t packh2(float lo, float hi) {
    uint32_t r;
    asm("{ .reg .f16 l, h; cvt.rn.f16.f32 l, %1; cvt.rn.f16.f32 h, %2; mov.b32 %0, {l, h}; }"
        : "=r"(r) : "f"(lo), "f"(hi));
    return r;
}
__device__ __forceinline__ uint32_t smem_u32(const void* p) {
    uint32_t a;
    asm("{ .reg .u64 t; cvta.to.shared.u64 t, %1; cvt.u32.u64 %0, t; }" : "=r"(a) : "l"(p));
    return a;
}
__device__ __forceinline__ void cpa16(uint32_t dst, const void* src) {
    asm volatile("cp.async.cg.shared.global [%0], [%1], 16;" :: "r"(dst), "l"(src) : "memory");
}

// ---------------------------------------------------------------------------
// Repack kernels: natural fp32 -> tf32-rounded fragment-ordered uint32.
// ---------------------------------------------------------------------------
__global__ void repack_A(const float* __restrict__ in, uint32_t* __restrict__ out, int K) {
    int gid  = blockIdx.x * 256 + threadIdx.x;      // one uint4 per thread
    int lane = gid & 31, tile = gid >> 5;
    int k8 = K >> 3;
    int tk = tile % k8, tm = tile / k8;
    int qr = lane >> 2, qc = lane & 3;
    const float* p = in + (size_t)(tm * 16 + qr) * K + tk * 8 + qc;
    uint4 u;
    u.x = f2tf(p[0]);
    u.y = f2tf(p[(size_t)8 * K]);
    u.z = f2tf(p[4]);
    u.w = f2tf(p[(size_t)8 * K + 4]);
    ((uint4*)out)[gid] = u;
}

__global__ void repack_B(const float* __restrict__ in, uint32_t* __restrict__ out, int K) {
    int gid  = blockIdx.x * 256 + threadIdx.x;      // one uint2 per thread
    int lane = gid & 31, tile = gid >> 5;
    int k8 = K >> 3;
    int tk = tile % k8, tn = tile / k8;
    int qr = lane >> 2, qc = lane & 3;
    const float* p = in + (size_t)(tn * 8 + qr) * K + tk * 8 + qc;
    uint2 u;
    u.x = f2tf(p[0]);
    u.y = f2tf(p[4]);
    ((uint2*)out)[gid] = u;
}

// ---------------------------------------------------------------------------
// Fragment-ordered tf32 GEMM (unchanged from R8): C = A @ W^T + bias.
// ---------------------------------------------------------------------------
#define GSMEM 65536

__device__ __forceinline__ void gemm_copy_chunk(
    uint32_t sb, int stage, const char* Ab, const char* Bb,
    int tm0, int tn0, int k8, int c, int tid)
{
    uint32_t dA = sb + stage * 32768;
    uint32_t dB = dA + 16384;
    int tkc = c * 4;
    #pragma unroll
    for (int i = 0; i < 4; i++) {
        int seg = i * 256 + tid;
        int t = seg >> 5, off = (seg & 31) * 16;
        cpa16(dA + t * 512 + off,
              Ab + (size_t)((tm0 + (t >> 2)) * k8 + tkc + (t & 3)) * 512 + off);
    }
    #pragma unroll
    for (int i = 0; i < 4; i++) {
        int seg = i * 256 + tid;
        int t = seg >> 4, off = (seg & 15) * 16;
        cpa16(dB + t * 256 + off,
              Bb + (size_t)((tn0 + (t >> 2)) * k8 + tkc + (t & 3)) * 256 + off);
    }
    asm volatile("cp.async.commit_group;" ::: "memory");
}

__global__ __launch_bounds__(256)
void gemm_frag(const uint32_t* __restrict__ Af, const uint32_t* __restrict__ Bf,
               const float* __restrict__ bias, float* __restrict__ C,
               int N, int K)
{
    extern __shared__ uint32_t smraw[];
    uint32_t sb = smem_u32(smraw);

    const int tid = threadIdx.x, wid = tid >> 5, lane = tid & 31;
    const int wm = wid >> 2, wn = wid & 3;
    const int qr = lane >> 2, qc = lane & 3;
    const int k8 = K >> 3;
    const int tm0 = blockIdx.y * 8, tn0 = blockIdx.x * 16;
    const int m0 = blockIdx.y * 128, n0 = blockIdx.x * 128;

    float acc[4][4][4];
    #pragma unroll
    for (int mi = 0; mi < 4; mi++)
        #pragma unroll
        for (int ni = 0; ni < 4; ni++)
            #pragma unroll
            for (int c = 0; c < 4; c++) acc[mi][ni][c] = 0.0f;

    const char* Ab = (const char*)Af;
    const char* Bb = (const char*)Bf;

    const int NC = K >> 5;
    gemm_copy_chunk(sb, 0, Ab, Bb, tm0, tn0, k8, 0, tid);

    for (int c = 0; c < NC; c++) {
        asm volatile("cp.async.wait_group 0;" ::: "memory");
        __syncthreads();
        if (c + 1 < NC)
            gemm_copy_chunk(sb, (c + 1) & 1, Ab, Bb, tm0, tn0, k8, c + 1, tid);

        uint32_t aB = sb + (c & 1) * 32768;
        uint32_t bB = aB + 16384;
        #pragma unroll
        for (int kt = 0; kt < 4; kt++) {
            uint4 af[4]; uint2 bf[4];
            #pragma unroll
            for (int mi = 0; mi < 4; mi++) {
                uint32_t addr = aB + (((wm * 4 + mi) * 4 + kt) * 512) + lane * 16;
                asm volatile("ld.shared.v4.u32 {%0,%1,%2,%3}, [%4];"
                    : "=r"(af[mi].x), "=r"(af[mi].y), "=r"(af[mi].z), "=r"(af[mi].w)
                    : "r"(addr));
            }
            #pragma unroll
            for (int ni = 0; ni < 4; ni++) {
                uint32_t addr = bB + (((wn * 4 + ni) * 4 + kt) * 256) + lane * 8;
                asm volatile("ld.shared.v2.u32 {%0,%1}, [%2];"
                    : "=r"(bf[ni].x), "=r"(bf[ni].y) : "r"(addr));
            }
            #pragma unroll
            for (int mi = 0; mi < 4; mi++)
                #pragma unroll
                for (int ni = 0; ni < 4; ni++)
                    mma_tf32(acc[mi][ni], &af[mi].x, &bf[ni].x);
        }
    }

    #pragma unroll
    for (int mi = 0; mi < 4; mi++) {
        int r0 = m0 + wm * 64 + mi * 16 + qr;
        #pragma unroll
        for (int ni = 0; ni < 4; ni++) {
            int col = n0 + wn * 32 + ni * 8 + 2 * qc;
            float b0 = bias[col], b1 = bias[col + 1];
            *(float2*)(C + (size_t)r0 * N + col) =
                make_float2(acc[mi][ni][0] + b0, acc[mi][ni][1] + b1);
            *(float2*)(C + (size_t)(r0 + 8) * N + col) =
                make_float2(acc[mi][ni][2] + b0, acc[mi][ni][3] + b1);
        }
    }
}

// ---------------------------------------------------------------------------
// fp16 tensor-core flash attention (m16n8k16), fp32 softmax (log2 domain).
// 128 queries x 1 head x 1 batch per block; 8 warps x 16 rows.
// KF groups (ni,kk): b0={K[ni8+qr][16kk+2qc],+1}, b1=d+8. uint2/lane.
// VF groups (kk,nd): b0={V[16kk+2qc][nd8+qr],V[16kk+2qc+1][nd8+qr]}, b1=k+8.
// S C-fragment == P A-fragment (no shuffles for PV).
// ---------------------------------------------------------------------------
#define BSTR 66

__global__ __launch_bounds__(256)
void flash_attn(const float* __restrict__ qkv, const int* __restrict__ maskp,
                float* __restrict__ att)
{
    __shared__ uint32_t KF[32 * BSTR];
    __shared__ uint32_t VF[32 * BSTR];

    const int tid  = threadIdx.x;
    const int wid  = tid >> 5;
    const int lane = tid & 31;
    const int qr   = lane >> 2;
    const int qc   = lane & 3;
    const int qblk = gridDim.x - 1 - blockIdx.x;     // heavy blocks first
    const int q0 = qblk * 128;
    const int h  = blockIdx.y;
    const int b  = blockIdx.z;
    const int mask = *maskp;
    const float* base = qkv + (size_t)b * S_LEN * 3 * DEMB;

    const int row0 = q0 + wid * 16 + qr;
    const int row1 = row0 + 8;
    const int wmax = q0 + wid * 16 + 15;

    // Q fragments (fp16 packed): [kk][a0..a3]
    uint32_t qf[4][4];
    {
        const float* q0p = base + (size_t)row0 * (3 * DEMB) + h * DHEAD;
        const float* q1p = base + (size_t)row1 * (3 * DEMB) + h * DHEAD;
        #pragma unroll
        for (int kk = 0; kk < 4; kk++) {
            int d0 = kk * 16 + 2 * qc;
            qf[kk][0] = packh2(q0p[d0], q0p[d0 + 1]);
            qf[kk][1] = packh2(q1p[d0], q1p[d0 + 1]);
            qf[kk][2] = packh2(q0p[d0 + 8], q0p[d0 + 9]);
            qf[kk][3] = packh2(q1p[d0 + 8], q1p[d0 + 9]);
        }
    }

    float o[8][4];
    #pragma unroll
    for (int nd = 0; nd < 8; nd++)
        #pragma unroll
        for (int c = 0; c < 4; c++) o[nd][c] = 0.0f;
    float m0r = -1e30f, m1r = -1e30f, l0 = 0.0f, l1 = 0.0f;

    const float SCL = 0.125f * 1.4426950408889634f;
    const int ntiles = mask ? (q0 / 64 + 2) : (S_LEN / 64);

    const int lrb = tid >> 4;            // 0..15
    const int c4  = (tid & 15) * 4;      // 0..60

    // prefetch tile 0
    float4 kreg[4], vreg[4];
    #pragma unroll
    for (int i = 0; i < 4; i++) {
        int r = i * 16 + lrb;
        const float* kp = base + (size_t)r * (3 * DEMB) + DEMB + h * DHEAD + c4;
        kreg[i] = *(const float4*)kp;
        vreg[i] = *(const float4*)(kp + DEMB);
    }

    __half* vf16 = (__half*)VF;

    for (int t = 0; t < ntiles; t++) {
        const int k0 = t * 64;
        __syncthreads();
        // scatter prefetched tile into fp16 fragment-order SMEM
        #pragma unroll
        for (int i = 0; i < 4; i++) {
            int r = i * 16 + lrb;
            // K: group (ni = r>>3, kk = c4>>4)
            {
                int g = (r >> 3) * 4 + (c4 >> 4);
                int cc = c4 & 15;
                int qc0 = (cc & 7) >> 1;            // 0 or 2
                int hi  = cc >> 3;                  // 0 or 1
                int lbase = (r & 7) * 4 + qc0;
                KF[g * BSTR + lbase * 2 + hi]       = packh2(kreg[i].x, kreg[i].y);
                KF[g * BSTR + (lbase + 1) * 2 + hi] = packh2(kreg[i].z, kreg[i].w);
            }
            // V: scalar fp16 scatter, group (kk = r>>4, nd = c>>3)
            {
                int rr = r & 15;
                int vhi  = rr >> 3;
                int qcv  = (rr & 7) >> 1;
                int slot = rr & 1;
                float vals[4] = {vreg[i].x, vreg[i].y, vreg[i].z, vreg[i].w};
                int gk = (r >> 4) * 8;
                #pragma unroll
                for (int j = 0; j < 4; j++) {
                    int cV = c4 + j;
                    int gv = gk + (cV >> 3);
                    int lv = (cV & 7) * 4 + qcv;
                    vf16[(gv * BSTR + lv * 2 + vhi) * 2 + slot] = __float2half_rn(vals[j]);
                }
            }
        }
        __syncthreads();
        // prefetch next tile (overlaps compute)
        if (t + 1 < ntiles) {
            int kn = (t + 1) * 64;
            #pragma unroll
            for (int i = 0; i < 4; i++) {
                int r = i * 16 + lrb;
                const float* kp = base + (size_t)(kn + r) * (3 * DEMB) + DEMB + h * DHEAD + c4;
                kreg[i] = *(const float4*)kp;
                vreg[i] = *(const float4*)(kp + DEMB);
            }
        }
        if (mask && k0 > wmax) continue;   // fully-masked tile for this warp

        // ----- S = Q @ K^T (fp16 mma, fp32 accum) -----
        float s[8][4];
        #pragma unroll
        for (int ni = 0; ni < 8; ni++)
            #pragma unroll
            for (int c = 0; c < 4; c++) s[ni][c] = 0.0f;
        #pragma unroll
        for (int kk = 0; kk < 4; kk++) {
            #pragma unroll
            for (int ni = 0; ni < 8; ni++) {
                uint2 kf = *(const uint2*)&KF[(ni * 4 + kk) * BSTR + lane * 2];
                mma_f16(s[ni], qf[kk], &kf.x);
            }
        }

        const bool domask = mask && (k0 + 63 > row0);
        #pragma unroll
        for (int ni = 0; ni < 8; ni++) {
            #pragma unroll
            for (int c = 0; c < 4; c++) s[ni][c] *= SCL;
            if (domask) {
                int col = k0 + ni * 8 + 2 * qc;
                if (col     > row0) s[ni][0] = -1e30f;
                if (col + 1 > row0) s[ni][1] = -1e30f;
                if (col     > row1) s[ni][2] = -1e30f;
                if (col + 1 > row1) s[ni][3] = -1e30f;
            }
        }

        // ----- online softmax (log2 domain) -----
        float mx0 = -1e30f, mx1 = -1e30f;
        #pragma unroll
        for (int ni = 0; ni < 8; ni++) {
            mx0 = fmaxf(mx0, fmaxf(s[ni][0], s[ni][1]));
            mx1 = fmaxf(mx1, fmaxf(s[ni][2], s[ni][3]));
        }
        mx0 = fmaxf(mx0, __shfl_xor_sync(0xffffffffu, mx0, 1));
        mx0 = fmaxf(mx0, __shfl_xor_sync(0xffffffffu, mx0, 2));
        mx1 = fmaxf(mx1, __shfl_xor_sync(0xffffffffu, mx1, 1));
        mx1 = fmaxf(mx1, __shfl_xor_sync(0xffffffffu, mx1, 2));

        float mn0 = fmaxf(m0r, mx0), mn1 = fmaxf(m1r, mx1);
        float al0 = ex2(m0r - mn0), al1 = ex2(m1r - mn1);
        m0r = mn0; m1r = mn1;

        float rs0 = 0.0f, rs1 = 0.0f;
        #pragma unroll
        for (int ni = 0; ni < 8; ni++) {
            float p0 = ex2(s[ni][0] - mn0);
            float p1 = ex2(s[ni][1] - mn0);
            float p2 = ex2(s[ni][2] - mn1);
            float p3 = ex2(s[ni][3] - mn1);
            rs0 += p0 + p1; rs1 += p2 + p3;
            s[ni][0] = p0; s[ni][1] = p1; s[ni][2] = p2; s[ni][3] = p3;
        }
        rs0 += __shfl_xor_sync(0xffffffffu, rs0, 1);
        rs0 += __shfl_xor_sync(0xffffffffu, rs0, 2);
        rs1 += __shfl_xor_sync(0xffffffffu, rs1, 1);
        rs1 += __shfl_xor_sync(0xffffffffu, rs1, 2);
        l0 = l0 * al0 + rs0;
        l1 = l1 * al1 + rs1;
        #pragma unroll
        for (int nd = 0; nd < 8; nd++) {
            o[nd][0] *= al0; o[nd][1] *= al0;
            o[nd][2] *= al1; o[nd][3] *= al1;
        }

        // ----- O += P @ V : S C-layout IS the fp16 A-layout (just pack) -----
        #pragma unroll
        for (int kk = 0; kk < 4; kk++) {
            uint32_t af[4];
            af[0] = packh2(s[2 * kk][0],     s[2 * kk][1]);
            af[1] = packh2(s[2 * kk][2],     s[2 * kk][3]);
            af[2] = packh2(s[2 * kk + 1][0], s[2 * kk + 1][1]);
            af[3] = packh2(s[2 * kk + 1][2], s[2 * kk + 1][3]);
            #pragma unroll
            for (int nd = 0; nd < 8; nd++) {
                uint2 vf = *(const uint2*)&VF[(kk * 8 + nd) * BSTR + lane * 2];
                mma_f16(o[nd], af, &vf.x);
            }
        }
    }

    // ----- normalize + store (natural layout) -----
    const float inv0 = 1.0f / l0, inv1 = 1.0f / l1;
    float* op0 = att + ((size_t)b * S_LEN + row0) * DEMB + h * DHEAD;
    float* op1 = att + ((size_t)b * S_LEN + row1) * DEMB + h * DHEAD;
    #pragma unroll
    for (int nd = 0; nd < 8; nd++) {
        *(float2*)(op0 + nd * 8 + 2 * qc) = make_float2(o[nd][0] * inv0, o[nd][1] * inv0);
        *(float2*)(op1 + nd * 8 + 2 * qc) = make_float2(o[nd][2] * inv1, o[nd][3] * inv1);
    }
}

// ---------------------------------------------------------------------------
extern "C" void kernel_launch(void* const* d_in, const int* in_sizes, int n_in,
                              void* d_out, int out_size)
{
    const float* x     = (const float*)d_in[0];
    const float* w_in  = (const float*)d_in[1];
    const float* b_in  = (const float*)d_in[2];
    const float* w_out = (const float*)d_in[3];
    const float* b_out = (const float*)d_in[4];
    const int*   maskp = (const int*)d_in[5];
    float* out = (float*)d_out;

    void *qkv_p, *att_p, *xf_p, *attf_p, *wif_p, *wof_p;
    cudaGetSymbolAddress(&qkv_p, g_qkv);
    cudaGetSymbolAddress(&att_p, g_att);
    cudaGetSymbolAddress(&xf_p, g_xf);
    cudaGetSymbolAddress(&attf_p, g_attf);
    cudaGetSymbolAddress(&wif_p, g_wif);
    cudaGetSymbolAddress(&wof_p, g_wof);
    float*    qkv  = (float*)qkv_p;
    float*    att  = (float*)att_p;
    uint32_t* xf   = (uint32_t*)xf_p;
    uint32_t* attf = (uint32_t*)attf_p;
    uint32_t* wif  = (uint32_t*)wif_p;
    uint32_t* wof  = (uint32_t*)wof_p;

    cudaFuncSetAttribute(gemm_frag, cudaFuncAttributeMaxDynamicSharedMemorySize, GSMEM);

    // 0) repack inputs into fragment order (tf32-rounded)
    repack_A<<<MTOT * DEMB / 4 / 256, 256>>>(x, xf, DEMB);
    repack_B<<<3 * DEMB * DEMB / 2 / 256, 256>>>(w_in, wif, DEMB);
    repack_B<<<DEMB * DEMB / 2 / 256, 256>>>(w_out, wof, DEMB);

    // 1) QKV projection
    gemm_frag<<<dim3(3 * DEMB / 128, MTOT / 128), 256, GSMEM>>>(
        xf, wif, b_in, qkv, 3 * DEMB, DEMB);

    // 2) causal flash attention (fp16 tensor cores)
    flash_attn<<<dim3(S_LEN / 128, NHEADS, 2), 256>>>(qkv, maskp, att);

    // 3) repack attention output into A-frag order
    repack_A<<<MTOT * DEMB / 4 / 256, 256>>>(att, attf, DEMB);

    // 4) output projection
    gemm_frag<<<dim3(DEMB / 128, MTOT / 128), 256, GSMEM>>>(
        attf, wof, b_out, out, DEMB, DEMB);
}

// round 10
// speedup vs baseline: 7.0110x; 1.3511x over previous
#include <cuda_runtime.h>
#include <cuda_fp16.h>
#include <stdint.h>
#include <math.h>

#define S_LEN   2048
#define DEMB    1024
#define MTOT    4096            // BATCH * S_LEN
#define NHEADS  16
#define DHEAD   64

// ---------------- device scratch (allocation-free rule) ----------------
__device__ float    g_qkv [MTOT * 3 * DEMB];   // fp32 [B,S,3D]
__device__ float    g_att [MTOT * DEMB];       // attention out, natural
__device__ uint32_t g_xf  [MTOT * DEMB / 2];   // x in fp16 A-frag order
__device__ uint32_t g_attf[MTOT * DEMB / 2];   // att in fp16 A-frag order
__device__ uint32_t g_wif [3 * DEMB * DEMB / 2]; // w_in fp16 B-frag order
__device__ uint32_t g_wof [DEMB * DEMB / 2];   // w_out fp16 B-frag order

// ---------------- helpers ----------------
__device__ __forceinline__ float ex2(float x) {
    float y; asm("ex2.approx.f32 %0, %1;" : "=f"(y) : "f"(x)); return y;
}
__device__ __forceinline__ void mma_f16(float* c, const uint32_t* a, const uint32_t* b) {
    asm volatile(
        "mma.sync.aligned.m16n8k16.row.col.f32.f16.f16.f32 "
        "{%0,%1,%2,%3}, {%4,%5,%6,%7}, {%8,%9}, {%0,%1,%2,%3};"
        : "+f"(c[0]), "+f"(c[1]), "+f"(c[2]), "+f"(c[3])
        : "r"(a[0]), "r"(a[1]), "r"(a[2]), "r"(a[3]), "r"(b[0]), "r"(b[1]));
}
__device__ __forceinline__ uint32_t packh2(float lo, float hi) {
    uint32_t r;
    asm("{ .reg .f16 l, h; cvt.rn.f16.f32 l, %1; cvt.rn.f16.f32 h, %2; mov.b32 %0, {l, h}; }"
        : "=r"(r) : "f"(lo), "f"(hi));
    return r;
}
__device__ __forceinline__ uint32_t smem_u32(const void* p) {
    uint32_t a;
    asm("{ .reg .u64 t; cvta.to.shared.u64 t, %1; cvt.u32.u64 %0, t; }" : "=r"(a) : "l"(p));
    return a;
}
__device__ __forceinline__ void cpa16(uint32_t dst, const void* src) {
    asm volatile("cp.async.cg.shared.global [%0], [%1], 16;" :: "r"(dst), "l"(src) : "memory");
}

// ---------------------------------------------------------------------------
// Repack kernels: natural fp32 -> fp16-packed fragment-ordered words.
// A-frag (m16n8k16): tile (tm,tk16) 16x16; lane uint4:
//   x={A[qr][2qc],+1}, y={A[qr+8][2qc],+1}, z={A[qr][2qc+8],+9}, w={A[qr+8][2qc+8],+9}
// B-frag: tile (tn,tk16) 8x16; lane uint2:
//   x={W[qr][2qc],+1}, y={W[qr][2qc+8],+9}
// ---------------------------------------------------------------------------
__global__ void repack_A_h(const float* __restrict__ in, uint32_t* __restrict__ out, int K) {
    int gid  = blockIdx.x * 256 + threadIdx.x;      // one uint4 per thread
    int lane = gid & 31, tile = gid >> 5;
    int k16 = K >> 4;
    int tk = tile % k16, tm = tile / k16;
    int qr = lane >> 2, qc = lane & 3;
    const float* p = in + (size_t)(tm * 16 + qr) * K + tk * 16 + 2 * qc;
    uint4 u;
    u.x = packh2(p[0], p[1]);
    u.y = packh2(p[(size_t)8 * K], p[(size_t)8 * K + 1]);
    u.z = packh2(p[8], p[9]);
    u.w = packh2(p[(size_t)8 * K + 8], p[(size_t)8 * K + 9]);
    ((uint4*)out)[gid] = u;
}

__global__ void repack_B_h(const float* __restrict__ in, uint32_t* __restrict__ out, int K) {
    int gid  = blockIdx.x * 256 + threadIdx.x;      // one uint2 per thread
    int lane = gid & 31, tile = gid >> 5;
    int k16 = K >> 4;
    int tk = tile % k16, tn = tile / k16;
    int qr = lane >> 2, qc = lane & 3;
    const float* p = in + (size_t)(tn * 8 + qr) * K + tk * 16 + 2 * qc;
    uint2 u;
    u.x = packh2(p[0], p[1]);
    u.y = packh2(p[8], p[9]);
    ((uint2*)out)[gid] = u;
}

// ---------------------------------------------------------------------------
// Fragment-ordered fp16 GEMM: C[M,N] = A @ W^T + bias.
// 128x128 CTA tile, BK=64, 2-stage cp.async double buffer, 1 barrier/chunk.
// 8 warps: wm(2) x wn(4); warp tile 64x32 = 4x4 m16n8k16 frags.
// smem/stage: A 16KB (32 tiles x 512B) + B 16KB (64 tiles x 256B).
// ---------------------------------------------------------------------------
#define GSMEM 65536

__device__ __forceinline__ void gemm_copy_chunk(
    uint32_t sb, int stage, const char* Ab, const char* Bb,
    int tm0, int tn0, int k16, int c, int tid)
{
    uint32_t dA = sb + stage * 32768;
    uint32_t dB = dA + 16384;
    int tkc = c * 4;                       // first k16-tile of this chunk
    #pragma unroll
    for (int i = 0; i < 4; i++) {
        int seg = i * 256 + tid;
        int t = seg >> 5, off = (seg & 31) * 16;
        cpa16(dA + t * 512 + off,
              Ab + (size_t)((tm0 + (t >> 2)) * k16 + tkc + (t & 3)) * 512 + off);
    }
    #pragma unroll
    for (int i = 0; i < 4; i++) {
        int seg = i * 256 + tid;
        int t = seg >> 4, off = (seg & 15) * 16;
        cpa16(dB + t * 256 + off,
              Bb + (size_t)((tn0 + (t >> 2)) * k16 + tkc + (t & 3)) * 256 + off);
    }
    asm volatile("cp.async.commit_group;" ::: "memory");
}

__global__ __launch_bounds__(256)
void gemm_frag(const uint32_t* __restrict__ Af, const uint32_t* __restrict__ Bf,
               const float* __restrict__ bias, float* __restrict__ C,
               int N, int K)
{
    extern __shared__ uint32_t smraw[];
    uint32_t sb = smem_u32(smraw);

    const int tid = threadIdx.x, wid = tid >> 5, lane = tid & 31;
    const int wm = wid >> 2, wn = wid & 3;
    const int qr = lane >> 2, qc = lane & 3;
    const int k16 = K >> 4;
    const int tm0 = blockIdx.y * 8, tn0 = blockIdx.x * 16;
    const int m0 = blockIdx.y * 128, n0 = blockIdx.x * 128;

    float acc[4][4][4];
    #pragma unroll
    for (int mi = 0; mi < 4; mi++)
        #pragma unroll
        for (int ni = 0; ni < 4; ni++)
            #pragma unroll
            for (int c = 0; c < 4; c++) acc[mi][ni][c] = 0.0f;

    const char* Ab = (const char*)Af;
    const char* Bb = (const char*)Bf;

    const int NC = K >> 6;                 // 16 chunks of BK=64
    gemm_copy_chunk(sb, 0, Ab, Bb, tm0, tn0, k16, 0, tid);

    for (int c = 0; c < NC; c++) {
        asm volatile("cp.async.wait_group 0;" ::: "memory");
        __syncthreads();
        if (c + 1 < NC)
            gemm_copy_chunk(sb, (c + 1) & 1, Ab, Bb, tm0, tn0, k16, c + 1, tid);

        uint32_t aB = sb + (c & 1) * 32768;
        uint32_t bB = aB + 16384;
        #pragma unroll
        for (int kt = 0; kt < 4; kt++) {
            uint4 af[4]; uint2 bf[4];
            #pragma unroll
            for (int mi = 0; mi < 4; mi++) {
                uint32_t addr = aB + (((wm * 4 + mi) * 4 + kt) * 512) + lane * 16;
                asm volatile("ld.shared.v4.u32 {%0,%1,%2,%3}, [%4];"
                    : "=r"(af[mi].x), "=r"(af[mi].y), "=r"(af[mi].z), "=r"(af[mi].w)
                    : "r"(addr));
            }
            #pragma unroll
            for (int ni = 0; ni < 4; ni++) {
                uint32_t addr = bB + (((wn * 4 + ni) * 4 + kt) * 256) + lane * 8;
                asm volatile("ld.shared.v2.u32 {%0,%1}, [%2];"
                    : "=r"(bf[ni].x), "=r"(bf[ni].y) : "r"(addr));
            }
            #pragma unroll
            for (int mi = 0; mi < 4; mi++)
                #pragma unroll
                for (int ni = 0; ni < 4; ni++)
                    mma_f16(acc[mi][ni], &af[mi].x, &bf[ni].x);
        }
    }

    #pragma unroll
    for (int mi = 0; mi < 4; mi++) {
        int r0 = m0 + wm * 64 + mi * 16 + qr;
        #pragma unroll
        for (int ni = 0; ni < 4; ni++) {
            int col = n0 + wn * 32 + ni * 8 + 2 * qc;
            float b0 = bias[col], b1 = bias[col + 1];
            *(float2*)(C + (size_t)r0 * N + col) =
                make_float2(acc[mi][ni][0] + b0, acc[mi][ni][1] + b1);
            *(float2*)(C + (size_t)(r0 + 8) * N + col) =
                make_float2(acc[mi][ni][2] + b0, acc[mi][ni][3] + b1);
        }
    }
}

// ---------------------------------------------------------------------------
// fp16 tensor-core flash attention (m16n8k16), fp32 softmax (log2 domain).
// 128 queries x 1 head x 1 batch per block; 8 warps x 16 rows. (Unchanged R9.)
// ---------------------------------------------------------------------------
#define BSTR 66

__global__ __launch_bounds__(256)
void flash_attn(const float* __restrict__ qkv, const int* __restrict__ maskp,
                float* __restrict__ att)
{
    __shared__ uint32_t KF[32 * BSTR];
    __shared__ uint32_t VF[32 * BSTR];

    const int tid  = threadIdx.x;
    const int wid  = tid >> 5;
    const int lane = tid & 31;
    const int qr   = lane >> 2;
    const int qc   = lane & 3;
    const int qblk = gridDim.x - 1 - blockIdx.x;     // heavy blocks first
    const int q0 = qblk * 128;
    const int h  = blockIdx.y;
    const int b  = blockIdx.z;
    const int mask = *maskp;
    const float* base = qkv + (size_t)b * S_LEN * 3 * DEMB;

    const int row0 = q0 + wid * 16 + qr;
    const int row1 = row0 + 8;
    const int wmax = q0 + wid * 16 + 15;

    uint32_t qf[4][4];
    {
        const float* q0p = base + (size_t)row0 * (3 * DEMB) + h * DHEAD;
        const float* q1p = base + (size_t)row1 * (3 * DEMB) + h * DHEAD;
        #pragma unroll
        for (int kk = 0; kk < 4; kk++) {
            int d0 = kk * 16 + 2 * qc;
            qf[kk][0] = packh2(q0p[d0], q0p[d0 + 1]);
            qf[kk][1] = packh2(q1p[d0], q1p[d0 + 1]);
            qf[kk][2] = packh2(q0p[d0 + 8], q0p[d0 + 9]);
            qf[kk][3] = packh2(q1p[d0 + 8], q1p[d0 + 9]);
        }
    }

    float o[8][4];
    #pragma unroll
    for (int nd = 0; nd < 8; nd++)
        #pragma unroll
        for (int c = 0; c < 4; c++) o[nd][c] = 0.0f;
    float m0r = -1e30f, m1r = -1e30f, l0 = 0.0f, l1 = 0.0f;

    const float SCL = 0.125f * 1.4426950408889634f;
    const int ntiles = mask ? (q0 / 64 + 2) : (S_LEN / 64);

    const int lrb = tid >> 4;
    const int c4  = (tid & 15) * 4;

    float4 kreg[4], vreg[4];
    #pragma unroll
    for (int i = 0; i < 4; i++) {
        int r = i * 16 + lrb;
        const float* kp = base + (size_t)r * (3 * DEMB) + DEMB + h * DHEAD + c4;
        kreg[i] = *(const float4*)kp;
        vreg[i] = *(const float4*)(kp + DEMB);
    }

    __half* vf16 = (__half*)VF;

    for (int t = 0; t < ntiles; t++) {
        const int k0 = t * 64;
        __syncthreads();
        #pragma unroll
        for (int i = 0; i < 4; i++) {
            int r = i * 16 + lrb;
            {
                int g = (r >> 3) * 4 + (c4 >> 4);
                int cc = c4 & 15;
                int qc0 = (cc & 7) >> 1;
                int hi  = cc >> 3;
                int lbase = (r & 7) * 4 + qc0;
                KF[g * BSTR + lbase * 2 + hi]       = packh2(kreg[i].x, kreg[i].y);
                KF[g * BSTR + (lbase + 1) * 2 + hi] = packh2(kreg[i].z, kreg[i].w);
            }
            {
                int rr = r & 15;
                int vhi  = rr >> 3;
                int qcv  = (rr & 7) >> 1;
                int slot = rr & 1;
                float vals[4] = {vreg[i].x, vreg[i].y, vreg[i].z, vreg[i].w};
                int gk = (r >> 4) * 8;
                #pragma unroll
                for (int j = 0; j < 4; j++) {
                    int cV = c4 + j;
                    int gv = gk + (cV >> 3);
                    int lv = (cV & 7) * 4 + qcv;
                    vf16[(gv * BSTR + lv * 2 + vhi) * 2 + slot] = __float2half_rn(vals[j]);
                }
            }
        }
        __syncthreads();
        if (t + 1 < ntiles) {
            int kn = (t + 1) * 64;
            #pragma unroll
            for (int i = 0; i < 4; i++) {
                int r = i * 16 + lrb;
                const float* kp = base + (size_t)(kn + r) * (3 * DEMB) + DEMB + h * DHEAD + c4;
                kreg[i] = *(const float4*)kp;
                vreg[i] = *(const float4*)(kp + DEMB);
            }
        }
        if (mask && k0 > wmax) continue;

        float s[8][4];
        #pragma unroll
        for (int ni = 0; ni < 8; ni++)
            #pragma unroll
            for (int c = 0; c < 4; c++) s[ni][c] = 0.0f;
        #pragma unroll
        for (int kk = 0; kk < 4; kk++) {
            #pragma unroll
            for (int ni = 0; ni < 8; ni++) {
                uint2 kf = *(const uint2*)&KF[(ni * 4 + kk) * BSTR + lane * 2];
                mma_f16(s[ni], qf[kk], &kf.x);
            }
        }

        const bool domask = mask && (k0 + 63 > row0);
        #pragma unroll
        for (int ni = 0; ni < 8; ni++) {
            #pragma unroll
            for (int c = 0; c < 4; c++) s[ni][c] *= SCL;
            if (domask) {
                int col = k0 + ni * 8 + 2 * qc;
                if (col     > row0) s[ni][0] = -1e30f;
                if (col + 1 > row0) s[ni][1] = -1e30f;
                if (col     > row1) s[ni][2] = -1e30f;
                if (col + 1 > row1) s[ni][3] = -1e30f;
            }
        }

        float mx0 = -1e30f, mx1 = -1e30f;
        #pragma unroll
        for (int ni = 0; ni < 8; ni++) {
            mx0 = fmaxf(mx0, fmaxf(s[ni][0], s[ni][1]));
            mx1 = fmaxf(mx1, fmaxf(s[ni][2], s[ni][3]));
        }
        mx0 = fmaxf(mx0, __shfl_xor_sync(0xffffffffu, mx0, 1));
        mx0 = fmaxf(mx0, __shfl_xor_sync(0xffffffffu, mx0, 2));
        mx1 = fmaxf(mx1, __shfl_xor_sync(0xffffffffu, mx1, 1));
        mx1 = fmaxf(mx1, __shfl_xor_sync(0xffffffffu, mx1, 2));

        float mn0 = fmaxf(m0r, mx0), mn1 = fmaxf(m1r, mx1);
        float al0 = ex2(m0r - mn0), al1 = ex2(m1r - mn1);
        m0r = mn0; m1r = mn1;

        float rs0 = 0.0f, rs1 = 0.0f;
        #pragma unroll
        for (int ni = 0; ni < 8; ni++) {
            float p0 = ex2(s[ni][0] - mn0);
            float p1 = ex2(s[ni][1] - mn0);
            float p2 = ex2(s[ni][2] - mn1);
            float p3 = ex2(s[ni][3] - mn1);
            rs0 += p0 + p1; rs1 += p2 + p3;
            s[ni][0] = p0; s[ni][1] = p1; s[ni][2] = p2; s[ni][3] = p3;
        }
        rs0 += __shfl_xor_sync(0xffffffffu, rs0, 1);
        rs0 += __shfl_xor_sync(0xffffffffu, rs0, 2);
        rs1 += __shfl_xor_sync(0xffffffffu, rs1, 1);
        rs1 += __shfl_xor_sync(0xffffffffu, rs1, 2);
        l0 = l0 * al0 + rs0;
        l1 = l1 * al1 + rs1;
        #pragma unroll
        for (int nd = 0; nd < 8; nd++) {
            o[nd][0] *= al0; o[nd][1] *= al0;
            o[nd][2] *= al1; o[nd][3] *= al1;
        }

        #pragma unroll
        for (int kk = 0; kk < 4; kk++) {
            uint32_t af[4];
            af[0] = packh2(s[2 * kk][0],     s[2 * kk][1]);
            af[1] = packh2(s[2 * kk][2],     s[2 * kk][3]);
            af[2] = packh2(s[2 * kk + 1][0], s[2 * kk + 1][1]);
            af[3] = packh2(s[2 * kk + 1][2], s[2 * kk + 1][3]);
            #pragma unroll
            for (int nd = 0; nd < 8; nd++) {
                uint2 vf = *(const uint2*)&VF[(kk * 8 + nd) * BSTR + lane * 2];
                mma_f16(o[nd], af, &vf.x);
            }
        }
    }

    const float inv0 = 1.0f / l0, inv1 = 1.0f / l1;
    float* op0 = att + ((size_t)b * S_LEN + row0) * DEMB + h * DHEAD;
    float* op1 = att + ((size_t)b * S_LEN + row1) * DEMB + h * DHEAD;
    #pragma unroll
    for (int nd = 0; nd < 8; nd++) {
        *(float2*)(op0 + nd * 8 + 2 * qc) = make_float2(o[nd][0] * inv0, o[nd][1] * inv0);
        *(float2*)(op1 + nd * 8 + 2 * qc) = make_float2(o[nd][2] * inv1, o[nd][3] * inv1);
    }
}

// ---------------------------------------------------------------------------
extern "C" void kernel_launch(void* const* d_in, const int* in_sizes, int n_in,
                              void* d_out, int out_size)
{
    const float* x     = (const float*)d_in[0];
    const float* w_in  = (const float*)d_in[1];
    const float* b_in  = (const float*)d_in[2];
    const float* w_out = (const float*)d_in[3];
    const float* b_out = (const float*)d_in[4];
    const int*   maskp = (const int*)d_in[5];
    float* out = (float*)d_out;

    void *qkv_p, *att_p, *xf_p, *attf_p, *wif_p, *wof_p;
    cudaGetSymbolAddress(&qkv_p, g_qkv);
    cudaGetSymbolAddress(&att_p, g_att);
    cudaGetSymbolAddress(&xf_p, g_xf);
    cudaGetSymbolAddress(&attf_p, g_attf);
    cudaGetSymbolAddress(&wif_p, g_wif);
    cudaGetSymbolAddress(&wof_p, g_wof);
    float*    qkv  = (float*)qkv_p;
    float*    att  = (float*)att_p;
    uint32_t* xf   = (uint32_t*)xf_p;
    uint32_t* attf = (uint32_t*)attf_p;
    uint32_t* wif  = (uint32_t*)wif_p;
    uint32_t* wof  = (uint32_t*)wof_p;

    cudaFuncSetAttribute(gemm_frag, cudaFuncAttributeMaxDynamicSharedMemorySize, GSMEM);

    // 0) repack inputs into fp16 fragment order
    // A: one uint4 per (tile,lane): (M/16)*(K/16)*32 threads
    repack_A_h<<<(MTOT / 16) * (DEMB / 16) * 32 / 256, 256>>>(x, xf, DEMB);
    // B: one uint2 per (tile,lane): (N/8)*(K/16)*32 threads
    repack_B_h<<<(3 * DEMB / 8) * (DEMB / 16) * 32 / 256, 256>>>(w_in, wif, DEMB);
    repack_B_h<<<(DEMB / 8) * (DEMB / 16) * 32 / 256, 256>>>(w_out, wof, DEMB);

    // 1) QKV projection (fp16 tensor cores)
    gemm_frag<<<dim3(3 * DEMB / 128, MTOT / 128), 256, GSMEM>>>(
        xf, wif, b_in, qkv, 3 * DEMB, DEMB);

    // 2) causal flash attention (fp16 tensor cores)
    flash_attn<<<dim3(S_LEN / 128, NHEADS, 2), 256>>>(qkv, maskp, att);

    // 3) repack attention output into fp16 A-frag order
    repack_A_h<<<(MTOT / 16) * (DEMB / 16) * 32 / 256, 256>>>(att, attf, DEMB);

    // 4) output projection
    gemm_frag<<<dim3(DEMB / 128, MTOT / 128), 256, GSMEM>>>(
        attf, wof, b_out, out, DEMB, DEMB);
}

// round 11
// speedup vs baseline: 7.0610x; 1.0071x over previous
#include <cuda_runtime.h>
#include <cuda_fp16.h>
#include <stdint.h>
#include <math.h>

#define S_LEN   2048
#define DEMB    1024
#define MTOT    4096            // BATCH * S_LEN
#define NHEADS  16
#define DHEAD   64
#define D3      (3 * DEMB)

// ---------------- device scratch (allocation-free rule) ----------------
__device__ uint32_t g_qkvh[MTOT * D3 / 2];       // fp16 qkv, natural layout (half2 words)
__device__ uint32_t g_xf  [MTOT * DEMB / 2];     // x in fp16 A-frag order
__device__ uint32_t g_attf[MTOT * DEMB / 2];     // att in fp16 A-frag order (written by attn)
__device__ uint32_t g_wif [3 * DEMB * DEMB / 2]; // w_in fp16 B-frag order
__device__ uint32_t g_wof [DEMB * DEMB / 2];     // w_out fp16 B-frag order

// ---------------- helpers ----------------
__device__ __forceinline__ float ex2(float x) {
    float y; asm("ex2.approx.f32 %0, %1;" : "=f"(y) : "f"(x)); return y;
}
__device__ __forceinline__ void mma_f16(float* c, const uint32_t* a, const uint32_t* b) {
    asm volatile(
        "mma.sync.aligned.m16n8k16.row.col.f32.f16.f16.f32 "
        "{%0,%1,%2,%3}, {%4,%5,%6,%7}, {%8,%9}, {%0,%1,%2,%3};"
        : "+f"(c[0]), "+f"(c[1]), "+f"(c[2]), "+f"(c[3])
        : "r"(a[0]), "r"(a[1]), "r"(a[2]), "r"(a[3]), "r"(b[0]), "r"(b[1]));
}
__device__ __forceinline__ uint32_t packh2(float lo, float hi) {
    uint32_t r;
    asm("{ .reg .f16 l, h; cvt.rn.f16.f32 l, %1; cvt.rn.f16.f32 h, %2; mov.b32 %0, {l, h}; }"
        : "=r"(r) : "f"(lo), "f"(hi));
    return r;
}
__device__ __forceinline__ uint32_t smem_u32(const void* p) {
    uint32_t a;
    asm("{ .reg .u64 t; cvta.to.shared.u64 t, %1; cvt.u32.u64 %0, t; }" : "=r"(a) : "l"(p));
    return a;
}
__device__ __forceinline__ void cpa16(uint32_t dst, const void* src) {
    asm volatile("cp.async.cg.shared.global [%0], [%1], 16;" :: "r"(dst), "l"(src) : "memory");
}

// ---------------------------------------------------------------------------
// Repack kernels: natural fp32 -> fp16-packed fragment-ordered words.
// ---------------------------------------------------------------------------
__global__ void repack_A_h(const float* __restrict__ in, uint32_t* __restrict__ out, int K) {
    int gid  = blockIdx.x * 256 + threadIdx.x;      // one uint4 per thread
    int lane = gid & 31, tile = gid >> 5;
    int k16 = K >> 4;
    int tk = tile % k16, tm = tile / k16;
    int qr = lane >> 2, qc = lane & 3;
    const float* p = in + (size_t)(tm * 16 + qr) * K + tk * 16 + 2 * qc;
    uint4 u;
    u.x = packh2(p[0], p[1]);
    u.y = packh2(p[(size_t)8 * K], p[(size_t)8 * K + 1]);
    u.z = packh2(p[8], p[9]);
    u.w = packh2(p[(size_t)8 * K + 8], p[(size_t)8 * K + 9]);
    ((uint4*)out)[gid] = u;
}

__global__ void repack_B_h(const float* __restrict__ in, uint32_t* __restrict__ out, int K) {
    int gid  = blockIdx.x * 256 + threadIdx.x;      // one uint2 per thread
    int lane = gid & 31, tile = gid >> 5;
    int k16 = K >> 4;
    int tk = tile % k16, tn = tile / k16;
    int qr = lane >> 2, qc = lane & 3;
    const float* p = in + (size_t)(tn * 8 + qr) * K + tk * 16 + 2 * qc;
    uint2 u;
    u.x = packh2(p[0], p[1]);
    u.y = packh2(p[8], p[9]);
    ((uint2*)out)[gid] = u;
}

// ---------------------------------------------------------------------------
// Fragment-ordered fp16 GEMM: C = A @ W^T + bias.
// 128x128 CTA tile, BK=64, 2-stage cp.async double buffer.
// half_out: 1 -> C is uint32* (fp16 half2 natural layout); 0 -> float*.
// ---------------------------------------------------------------------------
#define GSMEM 65536

__device__ __forceinline__ void gemm_copy_chunk(
    uint32_t sb, int stage, const char* Ab, const char* Bb,
    int tm0, int tn0, int k16, int c, int tid)
{
    uint32_t dA = sb + stage * 32768;
    uint32_t dB = dA + 16384;
    int tkc = c * 4;
    #pragma unroll
    for (int i = 0; i < 4; i++) {
        int seg = i * 256 + tid;
        int t = seg >> 5, off = (seg & 31) * 16;
        cpa16(dA + t * 512 + off,
              Ab + (size_t)((tm0 + (t >> 2)) * k16 + tkc + (t & 3)) * 512 + off);
    }
    #pragma unroll
    for (int i = 0; i < 4; i++) {
        int seg = i * 256 + tid;
        int t = seg >> 4, off = (seg & 15) * 16;
        cpa16(dB + t * 256 + off,
              Bb + (size_t)((tn0 + (t >> 2)) * k16 + tkc + (t & 3)) * 256 + off);
    }
    asm volatile("cp.async.commit_group;" ::: "memory");
}

__global__ __launch_bounds__(256)
void gemm_frag(const uint32_t* __restrict__ Af, const uint32_t* __restrict__ Bf,
               const float* __restrict__ bias, void* __restrict__ Cout,
               int N, int K, int half_out)
{
    extern __shared__ uint32_t smraw[];
    uint32_t sb = smem_u32(smraw);

    const int tid = threadIdx.x, wid = tid >> 5, lane = tid & 31;
    const int wm = wid >> 2, wn = wid & 3;
    const int qr = lane >> 2, qc = lane & 3;
    const int k16 = K >> 4;
    const int tm0 = blockIdx.y * 8, tn0 = blockIdx.x * 16;
    const int m0 = blockIdx.y * 128, n0 = blockIdx.x * 128;

    float acc[4][4][4];
    #pragma unroll
    for (int mi = 0; mi < 4; mi++)
        #pragma unroll
        for (int ni = 0; ni < 4; ni++)
            #pragma unroll
            for (int c = 0; c < 4; c++) acc[mi][ni][c] = 0.0f;

    const char* Ab = (const char*)Af;
    const char* Bb = (const char*)Bf;

    const int NC = K >> 6;
    gemm_copy_chunk(sb, 0, Ab, Bb, tm0, tn0, k16, 0, tid);

    for (int c = 0; c < NC; c++) {
        asm volatile("cp.async.wait_group 0;" ::: "memory");
        __syncthreads();
        if (c + 1 < NC)
            gemm_copy_chunk(sb, (c + 1) & 1, Ab, Bb, tm0, tn0, k16, c + 1, tid);

        uint32_t aB = sb + (c & 1) * 32768;
        uint32_t bB = aB + 16384;
        #pragma unroll
        for (int kt = 0; kt < 4; kt++) {
            uint4 af[4]; uint2 bf[4];
            #pragma unroll
            for (int mi = 0; mi < 4; mi++) {
                uint32_t addr = aB + (((wm * 4 + mi) * 4 + kt) * 512) + lane * 16;
                asm volatile("ld.shared.v4.u32 {%0,%1,%2,%3}, [%4];"
                    : "=r"(af[mi].x), "=r"(af[mi].y), "=r"(af[mi].z), "=r"(af[mi].w)
                    : "r"(addr));
            }
            #pragma unroll
            for (int ni = 0; ni < 4; ni++) {
                uint32_t addr = bB + (((wn * 4 + ni) * 4 + kt) * 256) + lane * 8;
                asm volatile("ld.shared.v2.u32 {%0,%1}, [%2];"
                    : "=r"(bf[ni].x), "=r"(bf[ni].y) : "r"(addr));
            }
            #pragma unroll
            for (int mi = 0; mi < 4; mi++)
                #pragma unroll
                for (int ni = 0; ni < 4; ni++)
                    mma_f16(acc[mi][ni], &af[mi].x, &bf[ni].x);
        }
    }

    #pragma unroll
    for (int mi = 0; mi < 4; mi++) {
        int r0 = m0 + wm * 64 + mi * 16 + qr;
        #pragma unroll
        for (int ni = 0; ni < 4; ni++) {
            int col = n0 + wn * 32 + ni * 8 + 2 * qc;
            float b0 = bias[col], b1 = bias[col + 1];
            float v00 = acc[mi][ni][0] + b0, v01 = acc[mi][ni][1] + b1;
            float v10 = acc[mi][ni][2] + b0, v11 = acc[mi][ni][3] + b1;
            if (half_out) {
                uint32_t* Ch = (uint32_t*)Cout;
                Ch[((size_t)r0 * N + col) >> 1]       = packh2(v00, v01);
                Ch[((size_t)(r0 + 8) * N + col) >> 1] = packh2(v10, v11);
            } else {
                float* C = (float*)Cout;
                *(float2*)(C + (size_t)r0 * N + col)       = make_float2(v00, v01);
                *(float2*)(C + (size_t)(r0 + 8) * N + col) = make_float2(v10, v11);
            }
        }
    }
}

// ---------------------------------------------------------------------------
// fp16 flash attention (m16n8k16), fp32 softmax (log2 domain).
// Reads fp16 qkv (half2 words); writes attf directly in A-fragment order.
// 128 queries x 1 head x 1 batch per block; 8 warps x 16 rows.
// ---------------------------------------------------------------------------
#define BSTR 66

__global__ __launch_bounds__(256)
void flash_attn(const uint32_t* __restrict__ qkvh, const int* __restrict__ maskp,
                uint4* __restrict__ attf)
{
    __shared__ uint32_t KF[32 * BSTR];
    __shared__ uint32_t VF[32 * BSTR];

    const int tid  = threadIdx.x;
    const int wid  = tid >> 5;
    const int lane = tid & 31;
    const int qr   = lane >> 2;
    const int qc   = lane & 3;
    const int qblk = gridDim.x - 1 - blockIdx.x;     // heavy blocks first
    const int q0 = qblk * 128;
    const int h  = blockIdx.y;
    const int b  = blockIdx.z;
    const int mask = *maskp;
    const uint32_t* base = qkvh + (size_t)b * S_LEN * (D3 / 2);

    const int row0 = q0 + wid * 16 + qr;
    const int row1 = row0 + 8;
    const int wmax = q0 + wid * 16 + 15;

    // Q fragments: direct half2 loads (qkv already fp16)
    uint32_t qf[4][4];
    {
        const uint32_t* q0p = base + (size_t)row0 * (D3 / 2) + h * (DHEAD / 2);
        const uint32_t* q1p = base + (size_t)row1 * (D3 / 2) + h * (DHEAD / 2);
        #pragma unroll
        for (int kk = 0; kk < 4; kk++) {
            qf[kk][0] = q0p[kk * 8 + qc];
            qf[kk][1] = q1p[kk * 8 + qc];
            qf[kk][2] = q0p[kk * 8 + qc + 4];
            qf[kk][3] = q1p[kk * 8 + qc + 4];
        }
    }

    float o[8][4];
    #pragma unroll
    for (int nd = 0; nd < 8; nd++)
        #pragma unroll
        for (int c = 0; c < 4; c++) o[nd][c] = 0.0f;
    float m0r = -1e30f, m1r = -1e30f, l0 = 0.0f, l1 = 0.0f;

    const float SCL = 0.125f * 1.4426950408889634f;
    const int ntiles = mask ? (q0 / 64 + 2) : (S_LEN / 64);

    const int lrb = tid >> 4;            // 0..15
    const int c4  = (tid & 15) * 4;      // 0..60

    // prefetch tile 0 (uint2 = 4 halves)
    uint2 kreg[4], vreg[4];
    #pragma unroll
    for (int i = 0; i < 4; i++) {
        int r = i * 16 + lrb;
        const uint32_t* kp = base + (size_t)r * (D3 / 2) + (DEMB + h * DHEAD + c4) / 2;
        kreg[i] = *(const uint2*)kp;
        vreg[i] = *(const uint2*)(kp + DEMB / 2);
    }

    __half* vf16 = (__half*)VF;

    for (int t = 0; t < ntiles; t++) {
        const int k0 = t * 64;
        __syncthreads();
        // scatter prefetched tile into fragment-order SMEM (pure moves for K)
        #pragma unroll
        for (int i = 0; i < 4; i++) {
            int r = i * 16 + lrb;
            {
                int g = (r >> 3) * 4 + (c4 >> 4);
                int cc = c4 & 15;
                int qc0 = (cc & 7) >> 1;
                int hi  = cc >> 3;
                int lbase = (r & 7) * 4 + qc0;
                KF[g * BSTR + lbase * 2 + hi]       = kreg[i].x;
                KF[g * BSTR + (lbase + 1) * 2 + hi] = kreg[i].y;
            }
            {
                int rr = r & 15;
                int vhi  = rr >> 3;
                int qcv  = (rr & 7) >> 1;
                int slot = rr & 1;
                const __half* vh = (const __half*)&vreg[i];
                int gk = (r >> 4) * 8;
                #pragma unroll
                for (int j = 0; j < 4; j++) {
                    int cV = c4 + j;
                    int gv = gk + (cV >> 3);
                    int lv = (cV & 7) * 4 + qcv;
                    vf16[(gv * BSTR + lv * 2 + vhi) * 2 + slot] = vh[j];
                }
            }
        }
        __syncthreads();
        // prefetch next tile (overlaps compute)
        if (t + 1 < ntiles) {
            int kn = (t + 1) * 64;
            #pragma unroll
            for (int i = 0; i < 4; i++) {
                int r = i * 16 + lrb;
                const uint32_t* kp = base + (size_t)(kn + r) * (D3 / 2) + (DEMB + h * DHEAD + c4) / 2;
                kreg[i] = *(const uint2*)kp;
                vreg[i] = *(const uint2*)(kp + DEMB / 2);
            }
        }
        if (mask && k0 > wmax) continue;

        // ----- S = Q @ K^T -----
        float s[8][4];
        #pragma unroll
        for (int ni = 0; ni < 8; ni++)
            #pragma unroll
            for (int c = 0; c < 4; c++) s[ni][c] = 0.0f;
        #pragma unroll
        for (int kk = 0; kk < 4; kk++) {
            #pragma unroll
            for (int ni = 0; ni < 8; ni++) {
                uint2 kf = *(const uint2*)&KF[(ni * 4 + kk) * BSTR + lane * 2];
                mma_f16(s[ni], qf[kk], &kf.x);
            }
        }

        const bool domask = mask && (k0 + 63 > row0);
        #pragma unroll
        for (int ni = 0; ni < 8; ni++) {
            #pragma unroll
            for (int c = 0; c < 4; c++) s[ni][c] *= SCL;
            if (domask) {
                int col = k0 + ni * 8 + 2 * qc;
                if (col     > row0) s[ni][0] = -1e30f;
                if (col + 1 > row0) s[ni][1] = -1e30f;
                if (col     > row1) s[ni][2] = -1e30f;
                if (col + 1 > row1) s[ni][3] = -1e30f;
            }
        }

        // ----- online softmax (log2 domain) -----
        float mx0 = -1e30f, mx1 = -1e30f;
        #pragma unroll
        for (int ni = 0; ni < 8; ni++) {
            mx0 = fmaxf(mx0, fmaxf(s[ni][0], s[ni][1]));
            mx1 = fmaxf(mx1, fmaxf(s[ni][2], s[ni][3]));
        }
        mx0 = fmaxf(mx0, __shfl_xor_sync(0xffffffffu, mx0, 1));
        mx0 = fmaxf(mx0, __shfl_xor_sync(0xffffffffu, mx0, 2));
        mx1 = fmaxf(mx1, __shfl_xor_sync(0xffffffffu, mx1, 1));
        mx1 = fmaxf(mx1, __shfl_xor_sync(0xffffffffu, mx1, 2));

        float mn0 = fmaxf(m0r, mx0), mn1 = fmaxf(m1r, mx1);
        float al0 = ex2(m0r - mn0), al1 = ex2(m1r - mn1);
        m0r = mn0; m1r = mn1;

        float rs0 = 0.0f, rs1 = 0.0f;
        #pragma unroll
        for (int ni = 0; ni < 8; ni++) {
            float p0 = ex2(s[ni][0] - mn0);
            float p1 = ex2(s[ni][1] - mn0);
            float p2 = ex2(s[ni][2] - mn1);
            float p3 = ex2(s[ni][3] - mn1);
            rs0 += p0 + p1; rs1 += p2 + p3;
            s[ni][0] = p0; s[ni][1] = p1; s[ni][2] = p2; s[ni][3] = p3;
        }
        rs0 += __shfl_xor_sync(0xffffffffu, rs0, 1);
        rs0 += __shfl_xor_sync(0xffffffffu, rs0, 2);
        rs1 += __shfl_xor_sync(0xffffffffu, rs1, 1);
        rs1 += __shfl_xor_sync(0xffffffffu, rs1, 2);
        l0 = l0 * al0 + rs0;
        l1 = l1 * al1 + rs1;
        #pragma unroll
        for (int nd = 0; nd < 8; nd++) {
            o[nd][0] *= al0; o[nd][1] *= al0;
            o[nd][2] *= al1; o[nd][3] *= al1;
        }

        // ----- O += P @ V : S C-layout IS the fp16 A-layout -----
        #pragma unroll
        for (int kk = 0; kk < 4; kk++) {
            uint32_t af[4];
            af[0] = packh2(s[2 * kk][0],     s[2 * kk][1]);
            af[1] = packh2(s[2 * kk][2],     s[2 * kk][3]);
            af[2] = packh2(s[2 * kk + 1][0], s[2 * kk + 1][1]);
            af[3] = packh2(s[2 * kk + 1][2], s[2 * kk + 1][3]);
            #pragma unroll
            for (int nd = 0; nd < 8; nd++) {
                uint2 vf = *(const uint2*)&VF[(kk * 8 + nd) * BSTR + lane * 2];
                mma_f16(o[nd], af, &vf.x);
            }
        }
    }

    // ----- normalize + store DIRECTLY in A-fragment order (fp16) -----
    // Warp owns A-frag tile row tm = b*128 + q0/16 + wid; tiles tk = h*4 + j.
    const float inv0 = 1.0f / l0, inv1 = 1.0f / l1;
    const int tm = b * (S_LEN / 16) + q0 / 16 + wid;
    #pragma unroll
    for (int j = 0; j < 4; j++) {
        uint4 u;
        u.x = packh2(o[2 * j][0] * inv0,     o[2 * j][1] * inv0);
        u.y = packh2(o[2 * j][2] * inv1,     o[2 * j][3] * inv1);
        u.z = packh2(o[2 * j + 1][0] * inv0, o[2 * j + 1][1] * inv0);
        u.w = packh2(o[2 * j + 1][2] * inv1, o[2 * j + 1][3] * inv1);
        attf[(size_t)(tm * (DEMB / 16) + h * 4 + j) * 32 + lane] = u;
    }
}

// ---------------------------------------------------------------------------
extern "C" void kernel_launch(void* const* d_in, const int* in_sizes, int n_in,
                              void* d_out, int out_size)
{
    const float* x     = (const float*)d_in[0];
    const float* w_in  = (const float*)d_in[1];
    const float* b_in  = (const float*)d_in[2];
    const float* w_out = (const float*)d_in[3];
    const float* b_out = (const float*)d_in[4];
    const int*   maskp = (const int*)d_in[5];
    float* out = (float*)d_out;

    void *qkvh_p, *xf_p, *attf_p, *wif_p, *wof_p;
    cudaGetSymbolAddress(&qkvh_p, g_qkvh);
    cudaGetSymbolAddress(&xf_p, g_xf);
    cudaGetSymbolAddress(&attf_p, g_attf);
    cudaGetSymbolAddress(&wif_p, g_wif);
    cudaGetSymbolAddress(&wof_p, g_wof);
    uint32_t* qkvh = (uint32_t*)qkvh_p;
    uint32_t* xf   = (uint32_t*)xf_p;
    uint32_t* attf = (uint32_t*)attf_p;
    uint32_t* wif  = (uint32_t*)wif_p;
    uint32_t* wof  = (uint32_t*)wof_p;

    cudaFuncSetAttribute(gemm_frag, cudaFuncAttributeMaxDynamicSharedMemorySize, GSMEM);

    // 0) repack inputs into fp16 fragment order
    repack_A_h<<<(MTOT / 16) * (DEMB / 16) * 32 / 256, 256>>>(x, xf, DEMB);
    repack_B_h<<<(3 * DEMB / 8) * (DEMB / 16) * 32 / 256, 256>>>(w_in, wif, DEMB);
    repack_B_h<<<(DEMB / 8) * (DEMB / 16) * 32 / 256, 256>>>(w_out, wof, DEMB);

    // 1) QKV projection -> fp16 natural layout
    gemm_frag<<<dim3(3 * DEMB / 128, MTOT / 128), 256, GSMEM>>>(
        xf, wif, b_in, qkvh, 3 * DEMB, DEMB, 1);

    // 2) causal flash attention -> attf in A-frag order (no repack needed)
    flash_attn<<<dim3(S_LEN / 128, NHEADS, 2), 256>>>(qkvh, maskp, (uint4*)attf);

    // 3) output projection -> fp32 out
    gemm_frag<<<dim3(DEMB / 128, MTOT / 128), 256, GSMEM>>>(
        attf, wof, b_out, out, DEMB, DEMB, 0);
}

// round 13
// speedup vs baseline: 7.5030x; 1.0626x over previous
#include <cuda_runtime.h>
#include <cuda_fp16.h>
#include <stdint.h>
#include <math.h>

#define S_LEN   2048
#define DEMB    1024
#define MTOT    4096            // BATCH * S_LEN
#define NHEADS  16
#define DHEAD   64
#define D3      (3 * DEMB)

// ---------------- device scratch (allocation-free rule) ----------------
__device__ uint32_t g_qkvh[MTOT * D3 / 2];       // fp16 qkv, natural layout (half2 words)
__device__ uint32_t g_xf  [MTOT * DEMB / 2];     // x in fp16 A-frag order
__device__ uint32_t g_attf[MTOT * DEMB / 2];     // att in fp16 A-frag order (written by attn)
__device__ uint32_t g_wif [3 * DEMB * DEMB / 2]; // w_in fp16 B-frag order
__device__ uint32_t g_wof [DEMB * DEMB / 2];     // w_out fp16 B-frag order

// ---------------- helpers ----------------
__device__ __forceinline__ float ex2(float x) {
    float y; asm("ex2.approx.f32 %0, %1;" : "=f"(y) : "f"(x)); return y;
}
__device__ __forceinline__ void mma_f16(float* c, const uint32_t* a, const uint32_t* b) {
    asm volatile(
        "mma.sync.aligned.m16n8k16.row.col.f32.f16.f16.f32 "
        "{%0,%1,%2,%3}, {%4,%5,%6,%7}, {%8,%9}, {%0,%1,%2,%3};"
        : "+f"(c[0]), "+f"(c[1]), "+f"(c[2]), "+f"(c[3])
        : "r"(a[0]), "r"(a[1]), "r"(a[2]), "r"(a[3]), "r"(b[0]), "r"(b[1]));
}
__device__ __forceinline__ uint32_t packh2(float lo, float hi) {
    uint32_t r;
    asm("{ .reg .f16 l, h; cvt.rn.f16.f32 l, %1; cvt.rn.f16.f32 h, %2; mov.b32 %0, {l, h}; }"
        : "=r"(r) : "f"(lo), "f"(hi));
    return r;
}
__device__ __forceinline__ uint32_t smem_u32(const void* p) {
    uint32_t a;
    asm("{ .reg .u64 t; cvta.to.shared.u64 t, %1; cvt.u32.u64 %0, t; }" : "=r"(a) : "l"(p));
    return a;
}
__device__ __forceinline__ void cpa16(uint32_t dst, const void* src) {
    asm volatile("cp.async.cg.shared.global [%0], [%1], 16;" :: "r"(dst), "l"(src) : "memory");
}

// ---------------------------------------------------------------------------
// Repack kernels: natural fp32 -> fp16-packed fragment-ordered words.
// ---------------------------------------------------------------------------
__global__ void repack_A_h(const float* __restrict__ in, uint32_t* __restrict__ out, int K) {
    int gid  = blockIdx.x * 256 + threadIdx.x;      // one uint4 per thread
    int lane = gid & 31, tile = gid >> 5;
    int k16 = K >> 4;
    int tk = tile % k16, tm = tile / k16;
    int qr = lane >> 2, qc = lane & 3;
    const float* p = in + (size_t)(tm * 16 + qr) * K + tk * 16 + 2 * qc;
    uint4 u;
    u.x = packh2(p[0], p[1]);
    u.y = packh2(p[(size_t)8 * K], p[(size_t)8 * K + 1]);
    u.z = packh2(p[8], p[9]);
    u.w = packh2(p[(size_t)8 * K + 8], p[(size_t)8 * K + 9]);
    ((uint4*)out)[gid] = u;
}

__global__ void repack_B_h(const float* __restrict__ in, uint32_t* __restrict__ out, int K) {
    int gid  = blockIdx.x * 256 + threadIdx.x;      // one uint2 per thread
    int lane = gid & 31, tile = gid >> 5;
    int k16 = K >> 4;
    int tk = tile % k16, tn = tile / k16;
    int qr = lane >> 2, qc = lane & 3;
    const float* p = in + (size_t)(tn * 8 + qr) * K + tk * 16 + 2 * qc;
    uint2 u;
    u.x = packh2(p[0], p[1]);
    u.y = packh2(p[8], p[9]);
    ((uint2*)out)[gid] = u;
}

// ---------------------------------------------------------------------------
// Fragment-ordered fp16 GEMM: C = A @ W^T + bias.
// 128x128 CTA tile, BK=64, 2-stage cp.async double buffer.
// HALF_OUT is a compile-time template (regs stay <=128; 2 CTAs/SM pinned).
// ---------------------------------------------------------------------------
#define GSMEM 65536

__device__ __forceinline__ void gemm_copy_chunk(
    uint32_t sb, int stage, const char* Ab, const char* Bb,
    int tm0, int tn0, int k16, int c, int tid)
{
    uint32_t dA = sb + stage * 32768;
    uint32_t dB = dA + 16384;
    int tkc = c * 4;
    #pragma unroll
    for (int i = 0; i < 4; i++) {
        int seg = i * 256 + tid;
        int t = seg >> 5, off = (seg & 31) * 16;
        cpa16(dA + t * 512 + off,
              Ab + (size_t)((tm0 + (t >> 2)) * k16 + tkc + (t & 3)) * 512 + off);
    }
    #pragma unroll
    for (int i = 0; i < 4; i++) {
        int seg = i * 256 + tid;
        int t = seg >> 4, off = (seg & 15) * 16;
        cpa16(dB + t * 256 + off,
              Bb + (size_t)((tn0 + (t >> 2)) * k16 + tkc + (t & 3)) * 256 + off);
    }
    asm volatile("cp.async.commit_group;" ::: "memory");
}

template <int HALF_OUT>
__global__ __launch_bounds__(256, 2)
void gemm_frag(const uint32_t* __restrict__ Af, const uint32_t* __restrict__ Bf,
               const float* __restrict__ bias, void* __restrict__ Cout,
               int N, int K)
{
    extern __shared__ uint32_t smraw[];
    uint32_t sb = smem_u32(smraw);

    const int tid = threadIdx.x, wid = tid >> 5, lane = tid & 31;
    const int wm = wid >> 2, wn = wid & 3;
    const int qr = lane >> 2, qc = lane & 3;
    const int k16 = K >> 4;
    const int tm0 = blockIdx.y * 8, tn0 = blockIdx.x * 16;
    const int m0 = blockIdx.y * 128, n0 = blockIdx.x * 128;

    float acc[4][4][4];
    #pragma unroll
    for (int mi = 0; mi < 4; mi++)
        #pragma unroll
        for (int ni = 0; ni < 4; ni++)
            #pragma unroll
            for (int c = 0; c < 4; c++) acc[mi][ni][c] = 0.0f;

    const char* Ab = (const char*)Af;
    const char* Bb = (const char*)Bf;

    const int NC = K >> 6;
    gemm_copy_chunk(sb, 0, Ab, Bb, tm0, tn0, k16, 0, tid);

    for (int c = 0; c < NC; c++) {
        asm volatile("cp.async.wait_group 0;" ::: "memory");
        __syncthreads();
        if (c + 1 < NC)
            gemm_copy_chunk(sb, (c + 1) & 1, Ab, Bb, tm0, tn0, k16, c + 1, tid);

        uint32_t aB = sb + (c & 1) * 32768;
        uint32_t bB = aB + 16384;
        #pragma unroll
        for (int kt = 0; kt < 4; kt++) {
            uint4 af[4]; uint2 bf[4];
            #pragma unroll
            for (int mi = 0; mi < 4; mi++) {
                uint32_t addr = aB + (((wm * 4 + mi) * 4 + kt) * 512) + lane * 16;
                asm volatile("ld.shared.v4.u32 {%0,%1,%2,%3}, [%4];"
                    : "=r"(af[mi].x), "=r"(af[mi].y), "=r"(af[mi].z), "=r"(af[mi].w)
                    : "r"(addr));
            }
            #pragma unroll
            for (int ni = 0; ni < 4; ni++) {
                uint32_t addr = bB + (((wn * 4 + ni) * 4 + kt) * 256) + lane * 8;
                asm volatile("ld.shared.v2.u32 {%0,%1}, [%2];"
                    : "=r"(bf[ni].x), "=r"(bf[ni].y) : "r"(addr));
            }
            #pragma unroll
            for (int mi = 0; mi < 4; mi++)
                #pragma unroll
                for (int ni = 0; ni < 4; ni++)
                    mma_f16(acc[mi][ni], &af[mi].x, &bf[ni].x);
        }
    }

    #pragma unroll
    for (int mi = 0; mi < 4; mi++) {
        int r0 = m0 + wm * 64 + mi * 16 + qr;
        #pragma unroll
        for (int ni = 0; ni < 4; ni++) {
            int col = n0 + wn * 32 + ni * 8 + 2 * qc;
            float b0 = bias[col], b1 = bias[col + 1];
            float v00 = acc[mi][ni][0] + b0, v01 = acc[mi][ni][1] + b1;
            float v10 = acc[mi][ni][2] + b0, v11 = acc[mi][ni][3] + b1;
            if (HALF_OUT) {
                uint32_t* Ch = (uint32_t*)Cout;
                Ch[((size_t)r0 * N + col) >> 1]       = packh2(v00, v01);
                Ch[((size_t)(r0 + 8) * N + col) >> 1] = packh2(v10, v11);
            } else {
                float* C = (float*)Cout;
                *(float2*)(C + (size_t)r0 * N + col)       = make_float2(v00, v01);
                *(float2*)(C + (size_t)(r0 + 8) * N + col) = make_float2(v10, v11);
            }
        }
    }
}

// ---------------------------------------------------------------------------
// fp16 flash attention (m16n8k16), fp32 softmax (log2 domain).
// Reads fp16 qkv (half2 words); writes attf directly in A-fragment order.
// 128 queries x 1 head x 1 batch per block; 8 warps x 16 rows.
// ---------------------------------------------------------------------------
#define BSTR 66

__global__ __launch_bounds__(256)
void flash_attn(const uint32_t* __restrict__ qkvh, const int* __restrict__ maskp,
                uint4* __restrict__ attf)
{
    __shared__ uint32_t KF[32 * BSTR];
    __shared__ uint32_t VF[32 * BSTR];

    const int tid  = threadIdx.x;
    const int wid  = tid >> 5;
    const int lane = tid & 31;
    const int qr   = lane >> 2;
    const int qc   = lane & 3;
    const int qblk = gridDim.x - 1 - blockIdx.x;     // heavy blocks first
    const int q0 = qblk * 128;
    const int h  = blockIdx.y;
    const int b  = blockIdx.z;
    const int mask = *maskp;
    const uint32_t* base = qkvh + (size_t)b * S_LEN * (D3 / 2);

    const int row0 = q0 + wid * 16 + qr;
    const int row1 = row0 + 8;
    const int wmax = q0 + wid * 16 + 15;

    // Q fragments: direct half2 loads (qkv already fp16)
    uint32_t qf[4][4];
    {
        const uint32_t* q0p = base + (size_t)row0 * (D3 / 2) + h * (DHEAD / 2);
        const uint32_t* q1p = base + (size_t)row1 * (D3 / 2) + h * (DHEAD / 2);
        #pragma unroll
        for (int kk = 0; kk < 4; kk++) {
            qf[kk][0] = q0p[kk * 8 + qc];
            qf[kk][1] = q1p[kk * 8 + qc];
            qf[kk][2] = q0p[kk * 8 + qc + 4];
            qf[kk][3] = q1p[kk * 8 + qc + 4];
        }
    }

    float o[8][4];
    #pragma unroll
    for (int nd = 0; nd < 8; nd++)
        #pragma unroll
        for (int c = 0; c < 4; c++) o[nd][c] = 0.0f;
    float m0r = -1e30f, m1r = -1e30f, l0 = 0.0f, l1 = 0.0f;

    const float SCL = 0.125f * 1.4426950408889634f;
    const int ntiles = mask ? (q0 / 64 + 2) : (S_LEN / 64);

    const int lrb = tid >> 4;            // 0..15
    const int c4  = (tid & 15) * 4;      // 0..60

    // prefetch tile 0 (uint2 = 4 halves)
    uint2 kreg[4], vreg[4];
    #pragma unroll
    for (int i = 0; i < 4; i++) {
        int r = i * 16 + lrb;
        const uint32_t* kp = base + (size_t)r * (D3 / 2) + (DEMB + h * DHEAD + c4) / 2;
        kreg[i] = *(const uint2*)kp;
        vreg[i] = *(const uint2*)(kp + DEMB / 2);
    }

    __half* vf16 = (__half*)VF;

    for (int t = 0; t < ntiles; t++) {
        const int k0 = t * 64;
        __syncthreads();
        // scatter prefetched tile into fragment-order SMEM (pure moves for K)
        #pragma unroll
        for (int i = 0; i < 4; i++) {
            int r = i * 16 + lrb;
            {
                int g = (r >> 3) * 4 + (c4 >> 4);
                int cc = c4 & 15;
                int qc0 = (cc & 7) >> 1;
                int hi  = cc >> 3;
                int lbase = (r & 7) * 4 + qc0;
                KF[g * BSTR + lbase * 2 + hi]       = kreg[i].x;
                KF[g * BSTR + (lbase + 1) * 2 + hi] = kreg[i].y;
            }
            {
                int rr = r & 15;
                int vhi  = rr >> 3;
                int qcv  = (rr & 7) >> 1;
                int slot = rr & 1;
                const __half* vh = (const __half*)&vreg[i];
                int gk = (r >> 4) * 8;
                #pragma unroll
                for (int j = 0; j < 4; j++) {
                    int cV = c4 + j;
                    int gv = gk + (cV >> 3);
                    int lv = (cV & 7) * 4 + qcv;
                    vf16[(gv * BSTR + lv * 2 + vhi) * 2 + slot] = vh[j];
                }
            }
        }
        __syncthreads();
        // prefetch next tile (overlaps compute)
        if (t + 1 < ntiles) {
            int kn = (t + 1) * 64;
            #pragma unroll
            for (int i = 0; i < 4; i++) {
                int r = i * 16 + lrb;
                const uint32_t* kp = base + (size_t)(kn + r) * (D3 / 2) + (DEMB + h * DHEAD + c4) / 2;
                kreg[i] = *(const uint2*)kp;
                vreg[i] = *(const uint2*)(kp + DEMB / 2);
            }
        }
        if (mask && k0 > wmax) continue;

        // ----- S = Q @ K^T -----
        float s[8][4];
        #pragma unroll
        for (int ni = 0; ni < 8; ni++)
            #pragma unroll
            for (int c = 0; c < 4; c++) s[ni][c] = 0.0f;
        #pragma unroll
        for (int kk = 0; kk < 4; kk++) {
            #pragma unroll
            for (int ni = 0; ni < 8; ni++) {
                uint2 kf = *(const uint2*)&KF[(ni * 4 + kk) * BSTR + lane * 2];
                mma_f16(s[ni], qf[kk], &kf.x);
            }
        }

        const bool domask = mask && (k0 + 63 > row0);
        #pragma unroll
        for (int ni = 0; ni < 8; ni++) {
            #pragma unroll
            for (int c = 0; c < 4; c++) s[ni][c] *= SCL;
            if (domask) {
                int col = k0 + ni * 8 + 2 * qc;
                if (col     > row0) s[ni][0] = -1e30f;
                if (col + 1 > row0) s[ni][1] = -1e30f;
                if (col     > row1) s[ni][2] = -1e30f;
                if (col + 1 > row1) s[ni][3] = -1e30f;
            }
        }

        // ----- online softmax (log2 domain) -----
        float mx0 = -1e30f, mx1 = -1e30f;
        #pragma unroll
        for (int ni = 0; ni < 8; ni++) {
            mx0 = fmaxf(mx0, fmaxf(s[ni][0], s[ni][1]));
            mx1 = fmaxf(mx1, fmaxf(s[ni][2], s[ni][3]));
        }
        mx0 = fmaxf(mx0, __shfl_xor_sync(0xffffffffu, mx0, 1));
        mx0 = fmaxf(mx0, __shfl_xor_sync(0xffffffffu, mx0, 2));
        mx1 = fmaxf(mx1, __shfl_xor_sync(0xffffffffu, mx1, 1));
        mx1 = fmaxf(mx1, __shfl_xor_sync(0xffffffffu, mx1, 2));

        float mn0 = fmaxf(m0r, mx0), mn1 = fmaxf(m1r, mx1);
        float al0 = ex2(m0r - mn0), al1 = ex2(m1r - mn1);
        m0r = mn0; m1r = mn1;

        float rs0 = 0.0f, rs1 = 0.0f;
        #pragma unroll
        for (int ni = 0; ni < 8; ni++) {
            float p0 = ex2(s[ni][0] - mn0);
            float p1 = ex2(s[ni][1] - mn0);
            float p2 = ex2(s[ni][2] - mn1);
            float p3 = ex2(s[ni][3] - mn1);
            rs0 += p0 + p1; rs1 += p2 + p3;
            s[ni][0] = p0; s[ni][1] = p1; s[ni][2] = p2; s[ni][3] = p3;
        }
        rs0 += __shfl_xor_sync(0xffffffffu, rs0, 1);
        rs0 += __shfl_xor_sync(0xffffffffu, rs0, 2);
        rs1 += __shfl_xor_sync(0xffffffffu, rs1, 1);
        rs1 += __shfl_xor_sync(0xffffffffu, rs1, 2);
        l0 = l0 * al0 + rs0;
        l1 = l1 * al1 + rs1;
        #pragma unroll
        for (int nd = 0; nd < 8; nd++) {
            o[nd][0] *= al0; o[nd][1] *= al0;
            o[nd][2] *= al1; o[nd][3] *= al1;
        }

        // ----- O += P @ V : S C-layout IS the fp16 A-layout -----
        #pragma unroll
        for (int kk = 0; kk < 4; kk++) {
            uint32_t af[4];
            af[0] = packh2(s[2 * kk][0],     s[2 * kk][1]);
            af[1] = packh2(s[2 * kk][2],     s[2 * kk][3]);
            af[2] = packh2(s[2 * kk + 1][0], s[2 * kk + 1][1]);
            af[3] = packh2(s[2 * kk + 1][2], s[2 * kk + 1][3]);
            #pragma unroll
            for (int nd = 0; nd < 8; nd++) {
                uint2 vf = *(const uint2*)&VF[(kk * 8 + nd) * BSTR + lane * 2];
                mma_f16(o[nd], af, &vf.x);
            }
        }
    }

    // ----- normalize + store DIRECTLY in A-fragment order (fp16) -----
    const float inv0 = 1.0f / l0, inv1 = 1.0f / l1;
    const int tm = b * (S_LEN / 16) + q0 / 16 + wid;
    #pragma unroll
    for (int j = 0; j < 4; j++) {
        uint4 u;
        u.x = packh2(o[2 * j][0] * inv0,     o[2 * j][1] * inv0);
        u.y = packh2(o[2 * j][2] * inv1,     o[2 * j][3] * inv1);
        u.z = packh2(o[2 * j + 1][0] * inv0, o[2 * j + 1][1] * inv0);
        u.w = packh2(o[2 * j + 1][2] * inv1, o[2 * j + 1][3] * inv1);
        attf[(size_t)(tm * (DEMB / 16) + h * 4 + j) * 32 + lane] = u;
    }
}

// ---------------------------------------------------------------------------
extern "C" void kernel_launch(void* const* d_in, const int* in_sizes, int n_in,
                              void* d_out, int out_size)
{
    const float* x     = (const float*)d_in[0];
    const float* w_in  = (const float*)d_in[1];
    const float* b_in  = (const float*)d_in[2];
    const float* w_out = (const float*)d_in[3];
    const float* b_out = (const float*)d_in[4];
    const int*   maskp = (const int*)d_in[5];
    float* out = (float*)d_out;

    void *qkvh_p, *xf_p, *attf_p, *wif_p, *wof_p;
    cudaGetSymbolAddress(&qkvh_p, g_qkvh);
    cudaGetSymbolAddress(&xf_p, g_xf);
    cudaGetSymbolAddress(&attf_p, g_attf);
    cudaGetSymbolAddress(&wif_p, g_wif);
    cudaGetSymbolAddress(&wof_p, g_wof);
    uint32_t* qkvh = (uint32_t*)qkvh_p;
    uint32_t* xf   = (uint32_t*)xf_p;
    uint32_t* attf = (uint32_t*)attf_p;
    uint32_t* wif  = (uint32_t*)wif_p;
    uint32_t* wof  = (uint32_t*)wof_p;

    cudaFuncSetAttribute(gemm_frag<1>, cudaFuncAttributeMaxDynamicSharedMemorySize, GSMEM);
    cudaFuncSetAttribute(gemm_frag<0>, cudaFuncAttributeMaxDynamicSharedMemorySize, GSMEM);

    // 0) repack inputs into fp16 fragment order
    repack_A_h<<<(MTOT / 16) * (DEMB / 16) * 32 / 256, 256>>>(x, xf, DEMB);
    repack_B_h<<<(3 * DEMB / 8) * (DEMB / 16) * 32 / 256, 256>>>(w_in, wif, DEMB);
    repack_B_h<<<(DEMB / 8) * (DEMB / 16) * 32 / 256, 256>>>(w_out, wof, DEMB);

    // 1) QKV projection -> fp16 natural layout
    gemm_frag<1><<<dim3(3 * DEMB / 128, MTOT / 128), 256, GSMEM>>>(
        xf, wif, b_in, qkvh, 3 * DEMB, DEMB);

    // 2) causal flash attention -> attf in A-frag order
    flash_attn<<<dim3(S_LEN / 128, NHEADS, 2), 256>>>(qkvh, maskp, (uint4*)attf);

    // 3) output projection -> fp32 out
    gemm_frag<0><<<dim3(DEMB / 128, MTOT / 128), 256, GSMEM>>>(
        attf, wof, b_out, out, DEMB, DEMB);
}